// round 1
// baseline (speedup 1.0000x reference)
#include <cuda_runtime.h>
#include <cuda_bf16.h>

// Problem constants (fixed shapes for this dataset instance)
#define MAXN 100000
#define MAXE 1600000
#define IN_DIM 128
#define HID 32
#define HEADS 4
#define HC 128          // HEADS*HID
#define OUT_DIM 32
#define NEG_SLOPE 0.2f
#define EPS 1e-16f

// ---------------- scratch (device globals; no allocation allowed) -----------
__device__ float g_h1[MAXN * HC];      // x @ W1, later reused as relu(out1+b1)
__device__ float g_agg1[MAXN * HC];    // layer-1 aggregation accumulator
__device__ float g_h2[MAXN * OUT_DIM]; // h1' @ W2
__device__ float g_asrc1[MAXN * HEADS];
__device__ float g_adst1[MAXN * HEADS];
__device__ float g_den1[MAXN * HEADS];
__device__ float g_asrc2[MAXN];
__device__ float g_adst2[MAXN];
__device__ float g_den2[MAXN];

// ---------------- utility ----------------------------------------------------
__global__ void zero_kernel(float* p, int n4) {
    int i = blockIdx.x * blockDim.x + threadIdx.x;
    if (i < n4) ((float4*)p)[i] = make_float4(0.f, 0.f, 0.f, 0.f);
}

// ---------------- GEMM1: h1[N,128] = x[N,128] @ W1[128,128] ------------------
// 64 nodes per block, 256 threads. W1 (64KB) + x tile (32KB) in dynamic smem.
__global__ void gemm1_kernel(const float* __restrict__ x,
                             const float* __restrict__ W, int N) {
    extern __shared__ float sm[];
    float* Ws = sm;            // 128*128
    float* xs = sm + 128 * 128; // 64*128
    float4* Ws4 = (float4*)Ws;
    float4* xs4 = (float4*)xs;
    const float4* W4 = (const float4*)W;
    const float4* x4 = (const float4*)x;

    int row0 = blockIdx.x * 64;
    for (int i = threadIdx.x; i < 128 * 32; i += 256) Ws4[i] = W4[i];
    for (int i = threadIdx.x; i < 64 * 32; i += 256) {
        int r = i >> 5;
        int g = row0 + r;
        xs4[i] = (g < N) ? x4[g * 32 + (i & 31)] : make_float4(0.f, 0.f, 0.f, 0.f);
    }
    __syncthreads();

    int tc = threadIdx.x & 31;   // column group: cols [4tc,4tc+4)
    int tr = threadIdx.x >> 5;   // row group: rows tr + 8*i
    float acc[8][4];
#pragma unroll
    for (int i = 0; i < 8; i++)
#pragma unroll
        for (int j = 0; j < 4; j++) acc[i][j] = 0.f;

#pragma unroll 4
    for (int k = 0; k < 128; k++) {
        float4 b = Ws4[k * 32 + tc];
#pragma unroll
        for (int i = 0; i < 8; i++) {
            float a = xs[(tr + 8 * i) * 128 + k];
            acc[i][0] += a * b.x;
            acc[i][1] += a * b.y;
            acc[i][2] += a * b.z;
            acc[i][3] += a * b.w;
        }
    }
    float4* h4 = (float4*)g_h1;
#pragma unroll
    for (int i = 0; i < 8; i++) {
        int row = row0 + tr + 8 * i;
        if (row < N)
            h4[row * 32 + tc] = make_float4(acc[i][0], acc[i][1], acc[i][2], acc[i][3]);
    }
}

// ---------------- GEMM2: h2[N,32] = h1relu[N,128] @ W2[128,32] ---------------
__global__ void gemm2_kernel(const float* __restrict__ W, int N) {
    extern __shared__ float sm[];
    float* Ws = sm;              // 128*32
    float* xs = sm + 128 * 32;   // 64*128
    float4* Ws4 = (float4*)Ws;
    float4* xs4 = (float4*)xs;
    const float4* W4 = (const float4*)W;
    const float4* x4 = (const float4*)g_h1;

    int row0 = blockIdx.x * 64;
    for (int i = threadIdx.x; i < 128 * 8; i += 256) Ws4[i] = W4[i];
    for (int i = threadIdx.x; i < 64 * 32; i += 256) {
        int r = i >> 5;
        int g = row0 + r;
        xs4[i] = (g < N) ? x4[g * 32 + (i & 31)] : make_float4(0.f, 0.f, 0.f, 0.f);
    }
    __syncthreads();

    int tc = threadIdx.x & 7;    // cols [4tc,4tc+4)
    int tr = threadIdx.x >> 3;   // rows tr + 32*i, i<2
    float acc[2][4];
#pragma unroll
    for (int i = 0; i < 2; i++)
#pragma unroll
        for (int j = 0; j < 4; j++) acc[i][j] = 0.f;

#pragma unroll 4
    for (int k = 0; k < 128; k++) {
        float4 b = Ws4[k * 8 + tc];
#pragma unroll
        for (int i = 0; i < 2; i++) {
            float a = xs[(tr + 32 * i) * 128 + k];
            acc[i][0] += a * b.x;
            acc[i][1] += a * b.y;
            acc[i][2] += a * b.z;
            acc[i][3] += a * b.w;
        }
    }
    float4* h4 = (float4*)g_h2;
#pragma unroll
    for (int i = 0; i < 2; i++) {
        int row = row0 + tr + 32 * i;
        if (row < N)
            h4[row * 8 + tc] = make_float4(acc[i][0], acc[i][1], acc[i][2], acc[i][3]);
    }
}

// ---------------- attention dots, layer 1 ------------------------------------
// one warp per node; computes a_src[n,h], a_dst[n,h] (h=0..3) and zeroes den1
__global__ void attn1_kernel(const float* __restrict__ att_s,
                             const float* __restrict__ att_d, int N) {
    int w = (blockIdx.x * blockDim.x + threadIdx.x) >> 5;
    int lane = threadIdx.x & 31;
    if (w >= N) return;
    float4 hv = ((const float4*)g_h1)[w * 32 + lane];
    float4 as = ((const float4*)att_s)[lane];
    float4 ad = ((const float4*)att_d)[lane];
    float ps = hv.x * as.x + hv.y * as.y + hv.z * as.z + hv.w * as.w;
    float pd = hv.x * ad.x + hv.y * ad.y + hv.z * ad.z + hv.w * ad.w;
    ps += __shfl_xor_sync(0xFFFFFFFFu, ps, 1);
    pd += __shfl_xor_sync(0xFFFFFFFFu, pd, 1);
    ps += __shfl_xor_sync(0xFFFFFFFFu, ps, 2);
    pd += __shfl_xor_sync(0xFFFFFFFFu, pd, 2);
    ps += __shfl_xor_sync(0xFFFFFFFFu, ps, 4);
    pd += __shfl_xor_sync(0xFFFFFFFFu, pd, 4);
    if ((lane & 7) == 0) {
        int h = lane >> 3;
        g_asrc1[w * 4 + h] = ps;
        g_adst1[w * 4 + h] = pd;
        g_den1[w * 4 + h] = 0.f;
    }
}

// ---------------- attention dots, layer 2 ------------------------------------
__global__ void attn2_kernel(const float* __restrict__ att_s,
                             const float* __restrict__ att_d, int N) {
    int w = (blockIdx.x * blockDim.x + threadIdx.x) >> 5;
    int lane = threadIdx.x & 31;
    if (w >= N) return;
    float hv = g_h2[w * 32 + lane];
    float ps = hv * att_s[lane];
    float pd = hv * att_d[lane];
#pragma unroll
    for (int o = 16; o > 0; o >>= 1) {
        ps += __shfl_xor_sync(0xFFFFFFFFu, ps, o);
        pd += __shfl_xor_sync(0xFFFFFFFFu, pd, o);
    }
    if (lane == 0) {
        g_asrc2[w] = ps;
        g_adst2[w] = pd;
        g_den2[w] = 0.f;
    }
}

// ---------------- edge pass, layer 1 ------------------------------------------
// one warp per edge (incl. implicit self-loops at ids >= E).
// agg1[dst] += exp(lrelu(e)) * h1[src];  den1[dst] += exp(lrelu(e))
__global__ void edge1_kernel(const int* __restrict__ src,
                             const int* __restrict__ dst, int E, int N) {
    int w = (blockIdx.x * blockDim.x + threadIdx.x) >> 5;
    int lane = threadIdx.x & 31;
    int EN = E + N;
    if (w >= EN) return;
    int s, d;
    if (w < E) { s = src[w]; d = dst[w]; }
    else       { s = w - E; d = s; }

    int h = lane >> 3;
    float e = g_asrc1[s * 4 + h] + g_adst1[d * 4 + h];
    e = (e > 0.f) ? e : NEG_SLOPE * e;
    float ex = __expf(e);
    if ((lane & 7) == 0) atomicAdd(&g_den1[d * 4 + h], ex);

    float4 v = ((const float4*)g_h1)[s * 32 + lane];
    float* ag = g_agg1 + (size_t)d * 128 + lane * 4;
    atomicAdd(ag + 0, ex * v.x);
    atomicAdd(ag + 1, ex * v.y);
    atomicAdd(ag + 2, ex * v.z);
    atomicAdd(ag + 3, ex * v.w);
}

// ---------------- edge pass, layer 2 (8 threads per edge) --------------------
__global__ void edge2_kernel(const int* __restrict__ src,
                             const int* __restrict__ dst,
                             float* __restrict__ out, int E, int N) {
    int t = blockIdx.x * blockDim.x + threadIdx.x;
    int eid = t >> 3;
    int li = t & 7;
    int EN = E + N;
    if (eid >= EN) return;
    int s, d;
    if (eid < E) { s = src[eid]; d = dst[eid]; }
    else         { s = eid - E; d = s; }

    float e = g_asrc2[s] + g_adst2[d];
    e = (e > 0.f) ? e : NEG_SLOPE * e;
    float ex = __expf(e);
    if (li == 0) atomicAdd(&g_den2[d], ex);

    float4 v = ((const float4*)g_h2)[s * 8 + li];
    float* ag = out + (size_t)d * 32 + li * 4;
    atomicAdd(ag + 0, ex * v.x);
    atomicAdd(ag + 1, ex * v.y);
    atomicAdd(ag + 2, ex * v.z);
    atomicAdd(ag + 3, ex * v.w);
}

// ---------------- finalize layer 1: h1 = relu(agg1/den1 + b1) ----------------
__global__ void finalize1_kernel(const float* __restrict__ b1, int N) {
    int idx = blockIdx.x * blockDim.x + threadIdx.x;
    if (idx >= N * 128) return;
    int n = idx >> 7;
    int c = idx & 127;
    float den = g_den1[n * 4 + (c >> 5)] + EPS;
    float v = g_agg1[idx] / den + b1[c];
    g_h1[idx] = (v > 0.f) ? v : 0.f;
}

// ---------------- finalize layer 2: out = out/den2 + b2 ----------------------
__global__ void finalize2_kernel(float* __restrict__ out,
                                 const float* __restrict__ b2, int N) {
    int idx = blockIdx.x * blockDim.x + threadIdx.x;
    if (idx >= N * 32) return;
    int n = idx >> 5;
    int c = idx & 31;
    out[idx] = out[idx] / (g_den2[n] + EPS) + b2[c];
}

// ---------------- launch ------------------------------------------------------
extern "C" void kernel_launch(void* const* d_in, const int* in_sizes, int n_in,
                              void* d_out, int out_size) {
    const float* x      = (const float*)d_in[0];
    const int*   ei     = (const int*)  d_in[1];
    const float* W1     = (const float*)d_in[2];
    const float* att_s1 = (const float*)d_in[3];
    const float* att_d1 = (const float*)d_in[4];
    const float* b1     = (const float*)d_in[5];
    const float* W2     = (const float*)d_in[6];
    const float* att_s2 = (const float*)d_in[7];
    const float* att_d2 = (const float*)d_in[8];
    const float* b2     = (const float*)d_in[9];

    int N = in_sizes[0] / IN_DIM;
    int E = in_sizes[1] / 2;
    const int* src = ei;
    const int* dst = ei + E;
    float* out = (float*)d_out;
    int EN = E + N;

    static bool attr_done = false;
    if (!attr_done) {
        cudaFuncSetAttribute(gemm1_kernel, cudaFuncAttributeMaxDynamicSharedMemorySize,
                             (128 * 128 + 64 * 128) * 4);
        cudaFuncSetAttribute(gemm2_kernel, cudaFuncAttributeMaxDynamicSharedMemorySize,
                             (128 * 32 + 64 * 128) * 4);
        attr_done = true;
    }

    // zero layer-1 aggregation buffer and output (atomic accumulators)
    {
        float* agg1_ptr;
        cudaGetSymbolAddress((void**)&agg1_ptr, g_agg1);
        int n4 = N * 128 / 4;
        zero_kernel<<<(n4 + 255) / 256, 256>>>(agg1_ptr, n4);
    }
    cudaMemsetAsync(d_out, 0, (size_t)N * 32 * sizeof(float), 0);

    // layer 1
    gemm1_kernel<<<(N + 63) / 64, 256, (128 * 128 + 64 * 128) * 4>>>(x, W1, N);
    attn1_kernel<<<(N * 32 + 255) / 256, 256>>>(att_s1, att_d1, N);
    edge1_kernel<<<((long long)EN * 32 + 255) / 256, 256>>>(src, dst, E, N);
    finalize1_kernel<<<(N * 128 + 255) / 256, 256>>>(b1, N);

    // layer 2
    gemm2_kernel<<<(N + 63) / 64, 256, (128 * 32 + 64 * 128) * 4>>>(W2, N);
    attn2_kernel<<<(N * 32 + 255) / 256, 256>>>(att_s2, att_d2, N);
    edge2_kernel<<<((long long)EN * 8 + 255) / 256, 256>>>(src, dst, out, E, N);
    finalize2_kernel<<<(N * 32 + 255) / 256, 256>>>(out, b2, N);
}

// round 2
// speedup vs baseline: 1.7007x; 1.7007x over previous
#include <cuda_runtime.h>
#include <cuda_bf16.h>

// Problem constants (fixed shapes for this dataset instance)
#define MAXN 100000
#define MAXE 1600000
#define IN_DIM 128
#define HID 32
#define HEADS 4
#define HC 128          // HEADS*HID
#define OUT_DIM 32
#define NEG_SLOPE 0.2f
#define EPS 1e-16f

// ---------------- scratch (device globals; no allocation allowed) -----------
__device__ float g_h1[MAXN * HC];      // x @ W1
__device__ float g_agg1[MAXN * HC];    // layer-1 aggregated + relu output (h1')
__device__ float g_h2[MAXN * OUT_DIM]; // h1' @ W2
__device__ float g_asrc1[MAXN * HEADS];
__device__ float g_adst1[MAXN * HEADS];
__device__ float g_asrc2[MAXN];
__device__ float g_adst2[MAXN];
// CSR build scratch
__device__ int g_deg[MAXN];
__device__ int g_rowptr[MAXN + 1];
__device__ int g_cursor[MAXN];
__device__ int g_esrc[MAXE + MAXN];

// ---------------- CSR build ---------------------------------------------------
__global__ void hist_kernel(const int* __restrict__ dst, int E, int EN) {
    int t = blockIdx.x * blockDim.x + threadIdx.x;
    if (t >= EN) return;
    int d = (t < E) ? dst[t] : (t - E);
    atomicAdd(&g_deg[d], 1);
}

// single-block exclusive scan over g_deg -> g_rowptr, g_cursor
__global__ void scan_kernel(int N) {
    __shared__ int ssum[1024];
    int t = threadIdx.x;
    int chunk = (N + 1023) / 1024;
    int lo = t * chunk;
    int hi = lo + chunk; if (hi > N) hi = N;
    int s = 0;
    for (int i = lo; i < hi; i++) s += g_deg[i];
    ssum[t] = s;
    __syncthreads();
    for (int off = 1; off < 1024; off <<= 1) {
        int v = (t >= off) ? ssum[t - off] : 0;
        __syncthreads();
        ssum[t] += v;
        __syncthreads();
    }
    int run = ssum[t] - s;  // exclusive prefix for this chunk
    for (int i = lo; i < hi; i++) {
        int d = g_deg[i];
        g_rowptr[i] = run;
        g_cursor[i] = run;
        run += d;
    }
    if (t == 1023) g_rowptr[N] = ssum[1023];
}

__global__ void scatter_kernel(const int* __restrict__ src,
                               const int* __restrict__ dst, int E, int EN) {
    int t = blockIdx.x * blockDim.x + threadIdx.x;
    if (t >= EN) return;
    int s, d;
    if (t < E) { s = src[t]; d = dst[t]; }
    else       { s = t - E;  d = s; }
    int pos = atomicAdd(&g_cursor[d], 1);
    g_esrc[pos] = s;
}

__global__ void zero_deg_kernel(int N) {
    int t = blockIdx.x * blockDim.x + threadIdx.x;
    if (t < N) g_deg[t] = 0;
}

// ---------------- GEMM1: h1[N,128] = x[N,128] @ W1[128,128] ------------------
__global__ void gemm1_kernel(const float* __restrict__ x,
                             const float* __restrict__ W, int N) {
    extern __shared__ float sm[];
    float* Ws = sm;             // 128*128
    float* xs = sm + 128 * 128; // 64*128
    float4* Ws4 = (float4*)Ws;
    float4* xs4 = (float4*)xs;
    const float4* W4 = (const float4*)W;
    const float4* x4 = (const float4*)x;

    int row0 = blockIdx.x * 64;
    for (int i = threadIdx.x; i < 128 * 32; i += 256) Ws4[i] = W4[i];
    for (int i = threadIdx.x; i < 64 * 32; i += 256) {
        int r = i >> 5;
        int g = row0 + r;
        xs4[i] = (g < N) ? x4[g * 32 + (i & 31)] : make_float4(0.f, 0.f, 0.f, 0.f);
    }
    __syncthreads();

    int tc = threadIdx.x & 31;
    int tr = threadIdx.x >> 5;
    float acc[8][4];
#pragma unroll
    for (int i = 0; i < 8; i++)
#pragma unroll
        for (int j = 0; j < 4; j++) acc[i][j] = 0.f;

#pragma unroll 4
    for (int k = 0; k < 128; k++) {
        float4 b = Ws4[k * 32 + tc];
#pragma unroll
        for (int i = 0; i < 8; i++) {
            float a = xs[(tr + 8 * i) * 128 + k];
            acc[i][0] += a * b.x;
            acc[i][1] += a * b.y;
            acc[i][2] += a * b.z;
            acc[i][3] += a * b.w;
        }
    }
    float4* h4 = (float4*)g_h1;
#pragma unroll
    for (int i = 0; i < 8; i++) {
        int row = row0 + tr + 8 * i;
        if (row < N)
            h4[row * 32 + tc] = make_float4(acc[i][0], acc[i][1], acc[i][2], acc[i][3]);
    }
}

// ---------------- GEMM2: h2[N,32] = h1'[N,128] @ W2[128,32] ------------------
__global__ void gemm2_kernel(const float* __restrict__ W, int N) {
    extern __shared__ float sm[];
    float* Ws = sm;              // 128*32
    float* xs = sm + 128 * 32;   // 64*128
    float4* Ws4 = (float4*)Ws;
    float4* xs4 = (float4*)xs;
    const float4* W4 = (const float4*)W;
    const float4* x4 = (const float4*)g_agg1;

    int row0 = blockIdx.x * 64;
    for (int i = threadIdx.x; i < 128 * 8; i += 256) Ws4[i] = W4[i];
    for (int i = threadIdx.x; i < 64 * 32; i += 256) {
        int r = i >> 5;
        int g = row0 + r;
        xs4[i] = (g < N) ? x4[g * 32 + (i & 31)] : make_float4(0.f, 0.f, 0.f, 0.f);
    }
    __syncthreads();

    int tc = threadIdx.x & 7;
    int tr = threadIdx.x >> 3;
    float acc[2][4];
#pragma unroll
    for (int i = 0; i < 2; i++)
#pragma unroll
        for (int j = 0; j < 4; j++) acc[i][j] = 0.f;

#pragma unroll 4
    for (int k = 0; k < 128; k++) {
        float4 b = Ws4[k * 8 + tc];
#pragma unroll
        for (int i = 0; i < 2; i++) {
            float a = xs[(tr + 32 * i) * 128 + k];
            acc[i][0] += a * b.x;
            acc[i][1] += a * b.y;
            acc[i][2] += a * b.z;
            acc[i][3] += a * b.w;
        }
    }
    float4* h4 = (float4*)g_h2;
#pragma unroll
    for (int i = 0; i < 2; i++) {
        int row = row0 + tr + 32 * i;
        if (row < N)
            h4[row * 8 + tc] = make_float4(acc[i][0], acc[i][1], acc[i][2], acc[i][3]);
    }
}

// ---------------- attention dots ----------------------------------------------
__global__ void attn1_kernel(const float* __restrict__ att_s,
                             const float* __restrict__ att_d, int N) {
    int w = (blockIdx.x * blockDim.x + threadIdx.x) >> 5;
    int lane = threadIdx.x & 31;
    if (w >= N) return;
    float4 hv = ((const float4*)g_h1)[w * 32 + lane];
    float4 as = ((const float4*)att_s)[lane];
    float4 ad = ((const float4*)att_d)[lane];
    float ps = hv.x * as.x + hv.y * as.y + hv.z * as.z + hv.w * as.w;
    float pd = hv.x * ad.x + hv.y * ad.y + hv.z * ad.z + hv.w * ad.w;
    ps += __shfl_xor_sync(0xFFFFFFFFu, ps, 1);
    pd += __shfl_xor_sync(0xFFFFFFFFu, pd, 1);
    ps += __shfl_xor_sync(0xFFFFFFFFu, ps, 2);
    pd += __shfl_xor_sync(0xFFFFFFFFu, pd, 2);
    ps += __shfl_xor_sync(0xFFFFFFFFu, ps, 4);
    pd += __shfl_xor_sync(0xFFFFFFFFu, pd, 4);
    if ((lane & 7) == 0) {
        int h = lane >> 3;
        g_asrc1[w * 4 + h] = ps;
        g_adst1[w * 4 + h] = pd;
    }
}

__global__ void attn2_kernel(const float* __restrict__ att_s,
                             const float* __restrict__ att_d, int N) {
    int w = (blockIdx.x * blockDim.x + threadIdx.x) >> 5;
    int lane = threadIdx.x & 31;
    if (w >= N) return;
    float hv = g_h2[w * 32 + lane];
    float ps = hv * att_s[lane];
    float pd = hv * att_d[lane];
#pragma unroll
    for (int o = 16; o > 0; o >>= 1) {
        ps += __shfl_xor_sync(0xFFFFFFFFu, ps, o);
        pd += __shfl_xor_sync(0xFFFFFFFFu, pd, o);
    }
    if (lane == 0) {
        g_asrc2[w] = ps;
        g_adst2[w] = pd;
    }
}

// ---------------- layer-1 aggregation: one warp per dst node ------------------
// g_agg1[n] = relu( (sum_e ex*h1[src]) / (sum_e ex) + b1 )
__global__ void agg1_kernel(const float* __restrict__ b1, int N) {
    int n = (blockIdx.x * blockDim.x + threadIdx.x) >> 5;
    int lane = threadIdx.x & 31;
    if (n >= N) return;
    int h = lane >> 3;
    float ad = g_adst1[n * 4 + h];
    int beg = g_rowptr[n];
    int end = g_rowptr[n + 1];
    const float4* h4 = (const float4*)g_h1;

    float4 acc = make_float4(0.f, 0.f, 0.f, 0.f);
    float den = 0.f;
    for (int i = beg; i < end; i++) {
        int s = g_esrc[i];
        float e = g_asrc1[s * 4 + h] + ad;
        e = (e > 0.f) ? e : NEG_SLOPE * e;
        float ex = __expf(e);
        den += ex;
        float4 v = h4[s * 32 + lane];
        acc.x += ex * v.x;
        acc.y += ex * v.y;
        acc.z += ex * v.z;
        acc.w += ex * v.w;
    }
    float inv = 1.f / (den + EPS);
    float4 bias = ((const float4*)b1)[lane];
    float4 r;
    r.x = fmaxf(acc.x * inv + bias.x, 0.f);
    r.y = fmaxf(acc.y * inv + bias.y, 0.f);
    r.z = fmaxf(acc.z * inv + bias.z, 0.f);
    r.w = fmaxf(acc.w * inv + bias.w, 0.f);
    ((float4*)g_agg1)[n * 32 + lane] = r;
}

// ---------------- layer-2 aggregation: one warp per dst node ------------------
// out[n] = (sum_e ex*h2[src]) / (sum_e ex) + b2
__global__ void agg2_kernel(float* __restrict__ out,
                            const float* __restrict__ b2, int N) {
    int n = (blockIdx.x * blockDim.x + threadIdx.x) >> 5;
    int lane = threadIdx.x & 31;
    if (n >= N) return;
    float ad = g_adst2[n];
    int beg = g_rowptr[n];
    int end = g_rowptr[n + 1];

    float acc = 0.f;
    float den = 0.f;
    for (int i = beg; i < end; i++) {
        int s = g_esrc[i];
        float e = g_asrc2[s] + ad;
        e = (e > 0.f) ? e : NEG_SLOPE * e;
        float ex = __expf(e);
        den += ex;
        acc += ex * g_h2[s * 32 + lane];
    }
    out[n * 32 + lane] = acc / (den + EPS) + b2[lane];
}

// ---------------- launch ------------------------------------------------------
extern "C" void kernel_launch(void* const* d_in, const int* in_sizes, int n_in,
                              void* d_out, int out_size) {
    const float* x      = (const float*)d_in[0];
    const int*   ei     = (const int*)  d_in[1];
    const float* W1     = (const float*)d_in[2];
    const float* att_s1 = (const float*)d_in[3];
    const float* att_d1 = (const float*)d_in[4];
    const float* b1     = (const float*)d_in[5];
    const float* W2     = (const float*)d_in[6];
    const float* att_s2 = (const float*)d_in[7];
    const float* att_d2 = (const float*)d_in[8];
    const float* b2     = (const float*)d_in[9];

    int N = in_sizes[0] / IN_DIM;
    int E = in_sizes[1] / 2;
    const int* src = ei;
    const int* dst = ei + E;
    float* out = (float*)d_out;
    int EN = E + N;

    static bool attr_done = false;
    if (!attr_done) {
        cudaFuncSetAttribute(gemm1_kernel, cudaFuncAttributeMaxDynamicSharedMemorySize,
                             (128 * 128 + 64 * 128) * 4);
        cudaFuncSetAttribute(gemm2_kernel, cudaFuncAttributeMaxDynamicSharedMemorySize,
                             (128 * 32 + 64 * 128) * 4);
        attr_done = true;
    }

    // ---- CSR build (dst-bucketed) ----
    zero_deg_kernel<<<(N + 255) / 256, 256>>>(N);
    hist_kernel<<<(EN + 255) / 256, 256>>>(dst, E, EN);
    scan_kernel<<<1, 1024>>>(N);
    scatter_kernel<<<(EN + 255) / 256, 256>>>(src, dst, E, EN);

    // ---- layer 1 ----
    gemm1_kernel<<<(N + 63) / 64, 256, (128 * 128 + 64 * 128) * 4>>>(x, W1, N);
    attn1_kernel<<<(N * 32 + 255) / 256, 256>>>(att_s1, att_d1, N);
    agg1_kernel<<<(N * 32 + 255) / 256, 256>>>(b1, N);

    // ---- layer 2 ----
    gemm2_kernel<<<(N + 63) / 64, 256, (128 * 32 + 64 * 128) * 4>>>(W2, N);
    attn2_kernel<<<(N * 32 + 255) / 256, 256>>>(att_s2, att_d2, N);
    agg2_kernel<<<(N * 32 + 255) / 256, 256>>>(out, b2, N);
}

// round 3
// speedup vs baseline: 2.7002x; 1.5877x over previous
#include <cuda_runtime.h>
#include <cuda_bf16.h>
#include <mma.h>

using namespace nvcuda;

#define MAXN 100000
#define NPAD (MAXN + 64)
#define MAXE 1600000
#define IN_DIM 128
#define HC 128
#define OUT_DIM 32
#define HEADS 4
#define NEG_SLOPE 0.2f
#define EPS 1e-16f

#define LDA 136            // 128+8 bf16 elems (272B rows; 16B-multiple)
#define LDB1 136
#define LDB2 40            // 32+8
#define GEMM1_SMEM ((64*LDA*2 + 128*LDB1*2) * 2)   // 104448 B
#define GEMM2_SMEM ((64*LDA*2 + 128*LDB2*2) * 2)   // 55296 B

// ---------------- scratch (device globals; zero-initialized) ----------------
__device__ float g_h1[NPAD * HC];       // x @ W1 (padded rows stay 0)
__device__ float g_agg1[NPAD * HC];     // layer-1 output h1' (relu'd)
__device__ float g_h2[NPAD * OUT_DIM];  // h1' @ W2
__device__ float g_asrc1[MAXN * HEADS];
__device__ float g_adst1[MAXN * HEADS];
__device__ float g_asrc2[MAXN];
__device__ float g_adst2[MAXN];
// CSR scratch
__device__ int g_deg[MAXN];
__device__ int g_rowptr[MAXN + 1];
__device__ int g_cursor[MAXN];
__device__ int g_esrc[MAXE + MAXN];
__device__ int g_btot[128];
__device__ int g_boff[128];

// ---------------- CSR build ---------------------------------------------------
__global__ void zero_deg_kernel(int N) {
    int t = blockIdx.x * blockDim.x + threadIdx.x;
    if (t < N) g_deg[t] = 0;
}

__global__ void hist_kernel(const int* __restrict__ dst, int E, int EN) {
    int t = blockIdx.x * blockDim.x + threadIdx.x;
    if (t >= EN) return;
    int d = (t < E) ? dst[t] : (t - E);
    atomicAdd(&g_deg[d], 1);
}

// per-block exclusive scan: rowptr[i] = excl-in-block, btot[blk] = block sum
__global__ void scan1_kernel(int N) {
    __shared__ int sh[1024];
    int i = blockIdx.x * 1024 + threadIdx.x;
    int v = (i < N) ? g_deg[i] : 0;
    sh[threadIdx.x] = v;
    __syncthreads();
#pragma unroll
    for (int off = 1; off < 1024; off <<= 1) {
        int t = (threadIdx.x >= off) ? sh[threadIdx.x - off] : 0;
        __syncthreads();
        sh[threadIdx.x] += t;
        __syncthreads();
    }
    if (i < N) g_rowptr[i] = sh[threadIdx.x] - v;  // exclusive
    if (threadIdx.x == 1023) g_btot[blockIdx.x] = sh[1023];
}

// scan 98 block totals (single block)
__global__ void scan2_kernel(int NB) {
    __shared__ int sh[128];
    int t = threadIdx.x;
    int v = (t < NB) ? g_btot[t] : 0;
    sh[t] = v;
    __syncthreads();
#pragma unroll
    for (int off = 1; off < 128; off <<= 1) {
        int u = (t >= off) ? sh[t - off] : 0;
        __syncthreads();
        sh[t] += u;
        __syncthreads();
    }
    if (t < NB) g_boff[t] = sh[t] - v;  // exclusive
}

__global__ void scan3_kernel(int N, int EN) {
    int i = blockIdx.x * blockDim.x + threadIdx.x;
    if (i < N) {
        int r = g_rowptr[i] + g_boff[i >> 10];
        g_rowptr[i] = r;
        g_cursor[i] = r;
    }
    if (i == 0) g_rowptr[N] = EN;
}

__global__ void scatter_kernel(const int* __restrict__ src,
                               const int* __restrict__ dst, int E, int EN) {
    int t = blockIdx.x * blockDim.x + threadIdx.x;
    if (t >= EN) return;
    int s, d;
    if (t < E) { s = src[t]; d = dst[t]; }
    else       { s = t - E;  d = s; }
    int pos = atomicAdd(&g_cursor[d], 1);
    g_esrc[pos] = s;
}

// ---------------- GEMM1 (WMMA bf16-split): h1[N,128] = x @ W1[128,128] -------
__global__ void gemm1_kernel(const float* __restrict__ x,
                             const float* __restrict__ W, int N) {
    extern __shared__ __nv_bfloat16 sm[];
    __nv_bfloat16* Ahi = sm;
    __nv_bfloat16* Alo = Ahi + 64 * LDA;
    __nv_bfloat16* Bhi = Alo + 64 * LDA;
    __nv_bfloat16* Blo = Bhi + 128 * LDB1;
    int tid = threadIdx.x;
    int row0 = blockIdx.x * 64;

    for (int i = tid; i < 128 * 128; i += 256) {
        int r = i >> 7, c = i & 127;
        float v = W[i];
        __nv_bfloat16 h = __float2bfloat16(v);
        Bhi[r * LDB1 + c] = h;
        Blo[r * LDB1 + c] = __float2bfloat16(v - __bfloat162float(h));
    }
    for (int i = tid; i < 64 * 128; i += 256) {
        int r = i >> 7, c = i & 127;
        int g = row0 + r;
        float v = (g < N) ? x[(size_t)g * 128 + c] : 0.f;
        __nv_bfloat16 h = __float2bfloat16(v);
        Ahi[r * LDA + c] = h;
        Alo[r * LDA + c] = __float2bfloat16(v - __bfloat162float(h));
    }
    __syncthreads();

    int w = tid >> 5;
    int wr = w >> 1, wc = w & 1;  // warp tile: rows wr*16, cols wc*64
    wmma::fragment<wmma::accumulator, 16, 16, 16, float> acc[4];
#pragma unroll
    for (int i = 0; i < 4; i++) wmma::fill_fragment(acc[i], 0.f);

#pragma unroll
    for (int k = 0; k < 8; k++) {
        wmma::fragment<wmma::matrix_a, 16, 16, 16, __nv_bfloat16, wmma::row_major> ah, al;
        wmma::load_matrix_sync(ah, Ahi + (wr * 16) * LDA + k * 16, LDA);
        wmma::load_matrix_sync(al, Alo + (wr * 16) * LDA + k * 16, LDA);
#pragma unroll
        for (int ct = 0; ct < 4; ct++) {
            wmma::fragment<wmma::matrix_b, 16, 16, 16, __nv_bfloat16, wmma::row_major> bh, bl;
            wmma::load_matrix_sync(bh, Bhi + (k * 16) * LDB1 + wc * 64 + ct * 16, LDB1);
            wmma::load_matrix_sync(bl, Blo + (k * 16) * LDB1 + wc * 64 + ct * 16, LDB1);
            wmma::mma_sync(acc[ct], ah, bh, acc[ct]);
            wmma::mma_sync(acc[ct], al, bh, acc[ct]);
            wmma::mma_sync(acc[ct], ah, bl, acc[ct]);
        }
    }
    float* outp = g_h1 + (size_t)(row0 + wr * 16) * 128 + wc * 64;
#pragma unroll
    for (int ct = 0; ct < 4; ct++)
        wmma::store_matrix_sync(outp + ct * 16, acc[ct], 128, wmma::mem_row_major);
}

// ---------------- GEMM2 (WMMA bf16-split): h2[N,32] = h1' @ W2[128,32] -------
__global__ void gemm2_kernel(const float* __restrict__ W, int N) {
    extern __shared__ __nv_bfloat16 sm[];
    __nv_bfloat16* Ahi = sm;
    __nv_bfloat16* Alo = Ahi + 64 * LDA;
    __nv_bfloat16* Bhi = Alo + 64 * LDA;
    __nv_bfloat16* Blo = Bhi + 128 * LDB2;
    int tid = threadIdx.x;
    int row0 = blockIdx.x * 64;

    for (int i = tid; i < 128 * 32; i += 256) {
        int r = i >> 5, c = i & 31;
        float v = W[i];
        __nv_bfloat16 h = __float2bfloat16(v);
        Bhi[r * LDB2 + c] = h;
        Blo[r * LDB2 + c] = __float2bfloat16(v - __bfloat162float(h));
    }
    for (int i = tid; i < 64 * 128; i += 256) {
        int r = i >> 7, c = i & 127;
        int g = row0 + r;
        float v = (g < N) ? g_agg1[(size_t)g * 128 + c] : 0.f;
        __nv_bfloat16 h = __float2bfloat16(v);
        Ahi[r * LDA + c] = h;
        Alo[r * LDA + c] = __float2bfloat16(v - __bfloat162float(h));
    }
    __syncthreads();

    int w = tid >> 5;
    int wr = w & 3, wc = w >> 2;  // rows wr*16, cols wc*16
    wmma::fragment<wmma::accumulator, 16, 16, 16, float> acc;
    wmma::fill_fragment(acc, 0.f);

#pragma unroll
    for (int k = 0; k < 8; k++) {
        wmma::fragment<wmma::matrix_a, 16, 16, 16, __nv_bfloat16, wmma::row_major> ah, al;
        wmma::fragment<wmma::matrix_b, 16, 16, 16, __nv_bfloat16, wmma::row_major> bh, bl;
        wmma::load_matrix_sync(ah, Ahi + (wr * 16) * LDA + k * 16, LDA);
        wmma::load_matrix_sync(al, Alo + (wr * 16) * LDA + k * 16, LDA);
        wmma::load_matrix_sync(bh, Bhi + (k * 16) * LDB2 + wc * 16, LDB2);
        wmma::load_matrix_sync(bl, Blo + (k * 16) * LDB2 + wc * 16, LDB2);
        wmma::mma_sync(acc, ah, bh, acc);
        wmma::mma_sync(acc, al, bh, acc);
        wmma::mma_sync(acc, ah, bl, acc);
    }
    float* outp = g_h2 + (size_t)(row0 + wr * 16) * 32 + wc * 16;
    wmma::store_matrix_sync(outp, acc, 32, wmma::mem_row_major);
}

// ---------------- attention dots ----------------------------------------------
__global__ void attn1_kernel(const float* __restrict__ att_s,
                             const float* __restrict__ att_d, int N) {
    int w = (blockIdx.x * blockDim.x + threadIdx.x) >> 5;
    int lane = threadIdx.x & 31;
    if (w >= N) return;
    float4 hv = ((const float4*)g_h1)[w * 32 + lane];
    float4 as = ((const float4*)att_s)[lane];
    float4 ad = ((const float4*)att_d)[lane];
    float ps = hv.x * as.x + hv.y * as.y + hv.z * as.z + hv.w * as.w;
    float pd = hv.x * ad.x + hv.y * ad.y + hv.z * ad.z + hv.w * ad.w;
    ps += __shfl_xor_sync(0xFFFFFFFFu, ps, 1);
    pd += __shfl_xor_sync(0xFFFFFFFFu, pd, 1);
    ps += __shfl_xor_sync(0xFFFFFFFFu, ps, 2);
    pd += __shfl_xor_sync(0xFFFFFFFFu, pd, 2);
    ps += __shfl_xor_sync(0xFFFFFFFFu, ps, 4);
    pd += __shfl_xor_sync(0xFFFFFFFFu, pd, 4);
    if ((lane & 7) == 0) {
        int h = lane >> 3;
        g_asrc1[w * 4 + h] = ps;
        g_adst1[w * 4 + h] = pd;
    }
}

__global__ void attn2_kernel(const float* __restrict__ att_s,
                             const float* __restrict__ att_d, int N) {
    int w = (blockIdx.x * blockDim.x + threadIdx.x) >> 5;
    int lane = threadIdx.x & 31;
    if (w >= N) return;
    float hv = g_h2[w * 32 + lane];
    float ps = hv * att_s[lane];
    float pd = hv * att_d[lane];
#pragma unroll
    for (int o = 16; o > 0; o >>= 1) {
        ps += __shfl_xor_sync(0xFFFFFFFFu, ps, o);
        pd += __shfl_xor_sync(0xFFFFFFFFu, pd, o);
    }
    if (lane == 0) {
        g_asrc2[w] = ps;
        g_adst2[w] = pd;
    }
}

// ---------------- layer-1 aggregation: one warp per dst node ------------------
__global__ void agg1_kernel(const float* __restrict__ b1, int N) {
    int n = (blockIdx.x * blockDim.x + threadIdx.x) >> 5;
    int lane = threadIdx.x & 31;
    if (n >= N) return;
    int h = lane >> 3;
    float ad = g_adst1[n * 4 + h];
    int beg = g_rowptr[n];
    int end = g_rowptr[n + 1];
    const float4* h4 = (const float4*)g_h1;

    float4 acc = make_float4(0.f, 0.f, 0.f, 0.f);
    float den = 0.f;
    int i = beg;
    for (; i + 2 <= end; i += 2) {
        int s0 = g_esrc[i];
        int s1 = g_esrc[i + 1];
        float e0 = g_asrc1[s0 * 4 + h] + ad;
        float e1 = g_asrc1[s1 * 4 + h] + ad;
        float4 v0 = h4[s0 * 32 + lane];
        float4 v1 = h4[s1 * 32 + lane];
        e0 = (e0 > 0.f) ? e0 : NEG_SLOPE * e0;
        e1 = (e1 > 0.f) ? e1 : NEG_SLOPE * e1;
        float ex0 = __expf(e0);
        float ex1 = __expf(e1);
        den += ex0 + ex1;
        acc.x += ex0 * v0.x + ex1 * v1.x;
        acc.y += ex0 * v0.y + ex1 * v1.y;
        acc.z += ex0 * v0.z + ex1 * v1.z;
        acc.w += ex0 * v0.w + ex1 * v1.w;
    }
    if (i < end) {
        int s = g_esrc[i];
        float e = g_asrc1[s * 4 + h] + ad;
        e = (e > 0.f) ? e : NEG_SLOPE * e;
        float ex = __expf(e);
        float4 v = h4[s * 32 + lane];
        den += ex;
        acc.x += ex * v.x; acc.y += ex * v.y;
        acc.z += ex * v.z; acc.w += ex * v.w;
    }
    float inv = 1.f / (den + EPS);
    float4 bias = ((const float4*)b1)[lane];
    float4 r;
    r.x = fmaxf(acc.x * inv + bias.x, 0.f);
    r.y = fmaxf(acc.y * inv + bias.y, 0.f);
    r.z = fmaxf(acc.z * inv + bias.z, 0.f);
    r.w = fmaxf(acc.w * inv + bias.w, 0.f);
    ((float4*)g_agg1)[n * 32 + lane] = r;
}

// ---------------- layer-2 aggregation: one warp per dst node ------------------
__global__ void agg2_kernel(float* __restrict__ out,
                            const float* __restrict__ b2, int N) {
    int n = (blockIdx.x * blockDim.x + threadIdx.x) >> 5;
    int lane = threadIdx.x & 31;
    if (n >= N) return;
    float ad = g_adst2[n];
    int beg = g_rowptr[n];
    int end = g_rowptr[n + 1];

    float acc = 0.f;
    float den = 0.f;
    int i = beg;
    for (; i + 4 <= end; i += 4) {
        int s0 = g_esrc[i], s1 = g_esrc[i + 1], s2 = g_esrc[i + 2], s3 = g_esrc[i + 3];
        float e0 = g_asrc2[s0] + ad, e1 = g_asrc2[s1] + ad;
        float e2 = g_asrc2[s2] + ad, e3 = g_asrc2[s3] + ad;
        float v0 = g_h2[s0 * 32 + lane], v1 = g_h2[s1 * 32 + lane];
        float v2 = g_h2[s2 * 32 + lane], v3 = g_h2[s3 * 32 + lane];
        e0 = (e0 > 0.f) ? e0 : NEG_SLOPE * e0;
        e1 = (e1 > 0.f) ? e1 : NEG_SLOPE * e1;
        e2 = (e2 > 0.f) ? e2 : NEG_SLOPE * e2;
        e3 = (e3 > 0.f) ? e3 : NEG_SLOPE * e3;
        float x0 = __expf(e0), x1 = __expf(e1), x2 = __expf(e2), x3 = __expf(e3);
        den += x0 + x1 + x2 + x3;
        acc += x0 * v0 + x1 * v1 + x2 * v2 + x3 * v3;
    }
    for (; i < end; i++) {
        int s = g_esrc[i];
        float e = g_asrc2[s] + ad;
        e = (e > 0.f) ? e : NEG_SLOPE * e;
        float ex = __expf(e);
        den += ex;
        acc += ex * g_h2[s * 32 + lane];
    }
    out[n * 32 + lane] = acc / (den + EPS) + b2[lane];
}

// ---------------- launch ------------------------------------------------------
extern "C" void kernel_launch(void* const* d_in, const int* in_sizes, int n_in,
                              void* d_out, int out_size) {
    const float* x      = (const float*)d_in[0];
    const int*   ei     = (const int*)  d_in[1];
    const float* W1     = (const float*)d_in[2];
    const float* att_s1 = (const float*)d_in[3];
    const float* att_d1 = (const float*)d_in[4];
    const float* b1     = (const float*)d_in[5];
    const float* W2     = (const float*)d_in[6];
    const float* att_s2 = (const float*)d_in[7];
    const float* att_d2 = (const float*)d_in[8];
    const float* b2     = (const float*)d_in[9];

    int N = in_sizes[0] / IN_DIM;
    int E = in_sizes[1] / 2;
    const int* src = ei;
    const int* dst = ei + E;
    float* out = (float*)d_out;
    int EN = E + N;
    int NB = (N + 1023) / 1024;

    static bool attr_done = false;
    if (!attr_done) {
        cudaFuncSetAttribute(gemm1_kernel, cudaFuncAttributeMaxDynamicSharedMemorySize, GEMM1_SMEM);
        cudaFuncSetAttribute(gemm2_kernel, cudaFuncAttributeMaxDynamicSharedMemorySize, GEMM2_SMEM);
        attr_done = true;
    }

    // ---- CSR build (dst-bucketed) ----
    zero_deg_kernel<<<(N + 255) / 256, 256>>>(N);
    hist_kernel<<<(EN + 255) / 256, 256>>>(dst, E, EN);
    scan1_kernel<<<NB, 1024>>>(N);
    scan2_kernel<<<1, 128>>>(NB);
    scan3_kernel<<<(N + 255) / 256, 256>>>(N, EN);
    scatter_kernel<<<(EN + 255) / 256, 256>>>(src, dst, E, EN);

    // ---- layer 1 ----
    gemm1_kernel<<<(N + 63) / 64, 256, GEMM1_SMEM>>>(x, W1, N);
    attn1_kernel<<<(N * 32 + 255) / 256, 256>>>(att_s1, att_d1, N);
    agg1_kernel<<<(N * 32 + 255) / 256, 256>>>(b1, N);

    // ---- layer 2 ----
    gemm2_kernel<<<(N + 63) / 64, 256, GEMM2_SMEM>>>(W2, N);
    attn2_kernel<<<(N * 32 + 255) / 256, 256>>>(att_s2, att_d2, N);
    agg2_kernel<<<(N * 32 + 255) / 256, 256>>>(out, b2, N);
}

// round 4
// speedup vs baseline: 2.7746x; 1.0276x over previous
#include <cuda_runtime.h>
#include <cuda_bf16.h>
#include <mma.h>
#include <stdint.h>

using namespace nvcuda;

#define MAXN 100000
#define NPAD (MAXN + 64)
#define MAXE 1600000
#define IN_DIM 128
#define HC 128
#define OUT_DIM 32
#define HEADS 4
#define NEG_SLOPE 0.2f
#define EPS 1e-16f

#define LDA 136
#define LDB1 136
#define LDB2 40
#define GEMM1_SMEM ((64*LDA*2 + 128*LDB1*2) * 2)
#define GEMM2_SMEM ((64*LDA*2 + 128*LDB2*2) * 2)

// ---------------- scratch (device globals) -----------------------------------
__device__ float g_h1[NPAD * HC];                 // x @ W1
__device__ __nv_bfloat16 g_h1bf[NPAD * HC];       // bf16 copy for agg1 gather
__device__ float g_agg1[NPAD * HC];               // layer-1 output h1' (relu'd)
__device__ float g_h2[NPAD * OUT_DIM];            // h1' @ W2
__device__ float g_asrc1[MAXN * HEADS];
__device__ float g_adst1[MAXN * HEADS];
__device__ float g_asrc2[MAXN];
__device__ float g_adst2[MAXN];
// CSR scratch
__device__ int g_deg[MAXN];
__device__ int g_rowptr[MAXN + 1];
__device__ int g_cursor[MAXN];
__device__ int g_esrc[MAXE + MAXN];
__device__ int g_btot[128];
__device__ int g_boff[128];

// ---------------- CSR build ---------------------------------------------------
__global__ void zero_deg_kernel(int N) {
    int t = blockIdx.x * blockDim.x + threadIdx.x;
    if (t < N) g_deg[t] = 0;
}

__global__ void hist_kernel(const int* __restrict__ dst, int E, int EN) {
    int t = blockIdx.x * blockDim.x + threadIdx.x;
    if (t >= EN) return;
    int d = (t < E) ? dst[t] : (t - E);
    atomicAdd(&g_deg[d], 1);
}

__global__ void scan1_kernel(int N) {
    __shared__ int sh[1024];
    int i = blockIdx.x * 1024 + threadIdx.x;
    int v = (i < N) ? g_deg[i] : 0;
    sh[threadIdx.x] = v;
    __syncthreads();
#pragma unroll
    for (int off = 1; off < 1024; off <<= 1) {
        int t = (threadIdx.x >= off) ? sh[threadIdx.x - off] : 0;
        __syncthreads();
        sh[threadIdx.x] += t;
        __syncthreads();
    }
    if (i < N) g_rowptr[i] = sh[threadIdx.x] - v;
    if (threadIdx.x == 1023) g_btot[blockIdx.x] = sh[1023];
}

__global__ void scan2_kernel(int NB) {
    __shared__ int sh[128];
    int t = threadIdx.x;
    int v = (t < NB) ? g_btot[t] : 0;
    sh[t] = v;
    __syncthreads();
#pragma unroll
    for (int off = 1; off < 128; off <<= 1) {
        int u = (t >= off) ? sh[t - off] : 0;
        __syncthreads();
        sh[t] += u;
        __syncthreads();
    }
    if (t < NB) g_boff[t] = sh[t] - v;
}

__global__ void scan3_kernel(int N, int EN) {
    int i = blockIdx.x * blockDim.x + threadIdx.x;
    if (i < N) {
        int r = g_rowptr[i] + g_boff[i >> 10];
        g_rowptr[i] = r;
        g_cursor[i] = r;
    }
    if (i == 0) g_rowptr[N] = EN;
}

__global__ void scatter_kernel(const int* __restrict__ src,
                               const int* __restrict__ dst, int E, int EN) {
    int t = blockIdx.x * blockDim.x + threadIdx.x;
    if (t >= EN) return;
    int s, d;
    if (t < E) { s = src[t]; d = dst[t]; }
    else       { s = t - E;  d = s; }
    int pos = atomicAdd(&g_cursor[d], 1);
    g_esrc[pos] = s;
}

// ---------------- GEMM1 (WMMA bf16-split): h1[N,128] = x @ W1[128,128] -------
__global__ void gemm1_kernel(const float* __restrict__ x,
                             const float* __restrict__ W, int N) {
    extern __shared__ __nv_bfloat16 sm[];
    __nv_bfloat16* Ahi = sm;
    __nv_bfloat16* Alo = Ahi + 64 * LDA;
    __nv_bfloat16* Bhi = Alo + 64 * LDA;
    __nv_bfloat16* Blo = Bhi + 128 * LDB1;
    int tid = threadIdx.x;
    int row0 = blockIdx.x * 64;

    for (int i = tid; i < 128 * 128; i += 256) {
        int r = i >> 7, c = i & 127;
        float v = W[i];
        __nv_bfloat16 h = __float2bfloat16(v);
        Bhi[r * LDB1 + c] = h;
        Blo[r * LDB1 + c] = __float2bfloat16(v - __bfloat162float(h));
    }
    for (int i = tid; i < 64 * 128; i += 256) {
        int r = i >> 7, c = i & 127;
        int g = row0 + r;
        float v = (g < N) ? x[(size_t)g * 128 + c] : 0.f;
        __nv_bfloat16 h = __float2bfloat16(v);
        Ahi[r * LDA + c] = h;
        Alo[r * LDA + c] = __float2bfloat16(v - __bfloat162float(h));
    }
    __syncthreads();

    int w = tid >> 5;
    int wr = w >> 1, wc = w & 1;
    wmma::fragment<wmma::accumulator, 16, 16, 16, float> acc[4];
#pragma unroll
    for (int i = 0; i < 4; i++) wmma::fill_fragment(acc[i], 0.f);

#pragma unroll
    for (int k = 0; k < 8; k++) {
        wmma::fragment<wmma::matrix_a, 16, 16, 16, __nv_bfloat16, wmma::row_major> ah, al;
        wmma::load_matrix_sync(ah, Ahi + (wr * 16) * LDA + k * 16, LDA);
        wmma::load_matrix_sync(al, Alo + (wr * 16) * LDA + k * 16, LDA);
#pragma unroll
        for (int ct = 0; ct < 4; ct++) {
            wmma::fragment<wmma::matrix_b, 16, 16, 16, __nv_bfloat16, wmma::row_major> bh, bl;
            wmma::load_matrix_sync(bh, Bhi + (k * 16) * LDB1 + wc * 64 + ct * 16, LDB1);
            wmma::load_matrix_sync(bl, Blo + (k * 16) * LDB1 + wc * 64 + ct * 16, LDB1);
            wmma::mma_sync(acc[ct], ah, bh, acc[ct]);
            wmma::mma_sync(acc[ct], al, bh, acc[ct]);
            wmma::mma_sync(acc[ct], ah, bl, acc[ct]);
        }
    }
    float* outp = g_h1 + (size_t)(row0 + wr * 16) * 128 + wc * 64;
#pragma unroll
    for (int ct = 0; ct < 4; ct++)
        wmma::store_matrix_sync(outp + ct * 16, acc[ct], 128, wmma::mem_row_major);
}

// ---------------- GEMM2 (WMMA bf16-split): h2[N,32] = h1' @ W2[128,32] -------
__global__ void gemm2_kernel(const float* __restrict__ W, int N) {
    extern __shared__ __nv_bfloat16 sm[];
    __nv_bfloat16* Ahi = sm;
    __nv_bfloat16* Alo = Ahi + 64 * LDA;
    __nv_bfloat16* Bhi = Alo + 64 * LDA;
    __nv_bfloat16* Blo = Bhi + 128 * LDB2;
    int tid = threadIdx.x;
    int row0 = blockIdx.x * 64;

    for (int i = tid; i < 128 * 32; i += 256) {
        int r = i >> 5, c = i & 31;
        float v = W[i];
        __nv_bfloat16 h = __float2bfloat16(v);
        Bhi[r * LDB2 + c] = h;
        Blo[r * LDB2 + c] = __float2bfloat16(v - __bfloat162float(h));
    }
    for (int i = tid; i < 64 * 128; i += 256) {
        int r = i >> 7, c = i & 127;
        int g = row0 + r;
        float v = (g < N) ? g_agg1[(size_t)g * 128 + c] : 0.f;
        __nv_bfloat16 h = __float2bfloat16(v);
        Ahi[r * LDA + c] = h;
        Alo[r * LDA + c] = __float2bfloat16(v - __bfloat162float(h));
    }
    __syncthreads();

    int w = tid >> 5;
    int wr = w & 3, wc = w >> 2;
    wmma::fragment<wmma::accumulator, 16, 16, 16, float> acc;
    wmma::fill_fragment(acc, 0.f);

#pragma unroll
    for (int k = 0; k < 8; k++) {
        wmma::fragment<wmma::matrix_a, 16, 16, 16, __nv_bfloat16, wmma::row_major> ah, al;
        wmma::fragment<wmma::matrix_b, 16, 16, 16, __nv_bfloat16, wmma::row_major> bh, bl;
        wmma::load_matrix_sync(ah, Ahi + (wr * 16) * LDA + k * 16, LDA);
        wmma::load_matrix_sync(al, Alo + (wr * 16) * LDA + k * 16, LDA);
        wmma::load_matrix_sync(bh, Bhi + (k * 16) * LDB2 + wc * 16, LDB2);
        wmma::load_matrix_sync(bl, Blo + (k * 16) * LDB2 + wc * 16, LDB2);
        wmma::mma_sync(acc, ah, bh, acc);
        wmma::mma_sync(acc, al, bh, acc);
        wmma::mma_sync(acc, ah, bl, acc);
    }
    float* outp = g_h2 + (size_t)(row0 + wr * 16) * 32 + wc * 16;
    wmma::store_matrix_sync(outp, acc, 32, wmma::mem_row_major);
}

// ---------------- attention dots + bf16 conversion ---------------------------
__global__ void attn1_kernel(const float* __restrict__ att_s,
                             const float* __restrict__ att_d, int N) {
    int w = (blockIdx.x * blockDim.x + threadIdx.x) >> 5;
    int lane = threadIdx.x & 31;
    if (w >= N) return;
    float4 hv = ((const float4*)g_h1)[w * 32 + lane];
    float4 as = ((const float4*)att_s)[lane];
    float4 ad = ((const float4*)att_d)[lane];
    float ps = hv.x * as.x + hv.y * as.y + hv.z * as.z + hv.w * as.w;
    float pd = hv.x * ad.x + hv.y * ad.y + hv.z * ad.z + hv.w * ad.w;
    ps += __shfl_xor_sync(0xFFFFFFFFu, ps, 1);
    pd += __shfl_xor_sync(0xFFFFFFFFu, pd, 1);
    ps += __shfl_xor_sync(0xFFFFFFFFu, ps, 2);
    pd += __shfl_xor_sync(0xFFFFFFFFu, pd, 2);
    ps += __shfl_xor_sync(0xFFFFFFFFu, ps, 4);
    pd += __shfl_xor_sync(0xFFFFFFFFu, pd, 4);
    // bf16 copy for the aggregation gather
    __nv_bfloat162 p0 = __floats2bfloat162_rn(hv.x, hv.y);
    __nv_bfloat162 p1 = __floats2bfloat162_rn(hv.z, hv.w);
    uint2 pk;
    pk.x = *(uint32_t*)&p0;
    pk.y = *(uint32_t*)&p1;
    ((uint2*)g_h1bf)[w * 32 + lane] = pk;
    if ((lane & 7) == 0) {
        int h = lane >> 3;
        g_asrc1[w * 4 + h] = ps;
        g_adst1[w * 4 + h] = pd;
    }
}

__global__ void attn2_kernel(const float* __restrict__ att_s,
                             const float* __restrict__ att_d, int N) {
    int w = (blockIdx.x * blockDim.x + threadIdx.x) >> 5;
    int lane = threadIdx.x & 31;
    if (w >= N) return;
    float hv = g_h2[w * 32 + lane];
    float ps = hv * att_s[lane];
    float pd = hv * att_d[lane];
#pragma unroll
    for (int o = 16; o > 0; o >>= 1) {
        ps += __shfl_xor_sync(0xFFFFFFFFu, ps, o);
        pd += __shfl_xor_sync(0xFFFFFFFFu, pd, o);
    }
    if (lane == 0) {
        g_asrc2[w] = ps;
        g_adst2[w] = pd;
    }
}

// ---------------- layer-1 aggregation (bf16 gather, fp32 accum) --------------
__global__ void agg1_kernel(const float* __restrict__ b1, int N) {
    int n = (blockIdx.x * blockDim.x + threadIdx.x) >> 5;
    int lane = threadIdx.x & 31;
    if (n >= N) return;
    int h = lane >> 3;
    float ad = g_adst1[n * 4 + h];
    int beg = g_rowptr[n];
    int end = g_rowptr[n + 1];
    const uint2* hb = (const uint2*)g_h1bf;

    float4 acc = make_float4(0.f, 0.f, 0.f, 0.f);
    float den = 0.f;
    int i = beg;
    for (; i + 2 <= end; i += 2) {
        int s0 = g_esrc[i];
        int s1 = g_esrc[i + 1];
        float e0 = g_asrc1[s0 * 4 + h] + ad;
        float e1 = g_asrc1[s1 * 4 + h] + ad;
        uint2 r0 = hb[s0 * 32 + lane];
        uint2 r1 = hb[s1 * 32 + lane];
        e0 = (e0 > 0.f) ? e0 : NEG_SLOPE * e0;
        e1 = (e1 > 0.f) ? e1 : NEG_SLOPE * e1;
        float ex0 = __expf(e0);
        float ex1 = __expf(e1);
        den += ex0 + ex1;
        float2 a0 = __bfloat1622float2(*(__nv_bfloat162*)&r0.x);
        float2 a1 = __bfloat1622float2(*(__nv_bfloat162*)&r0.y);
        float2 b0 = __bfloat1622float2(*(__nv_bfloat162*)&r1.x);
        float2 b1v = __bfloat1622float2(*(__nv_bfloat162*)&r1.y);
        acc.x += ex0 * a0.x + ex1 * b0.x;
        acc.y += ex0 * a0.y + ex1 * b0.y;
        acc.z += ex0 * a1.x + ex1 * b1v.x;
        acc.w += ex0 * a1.y + ex1 * b1v.y;
    }
    if (i < end) {
        int s = g_esrc[i];
        float e = g_asrc1[s * 4 + h] + ad;
        e = (e > 0.f) ? e : NEG_SLOPE * e;
        float ex = __expf(e);
        uint2 r0 = hb[s * 32 + lane];
        float2 a0 = __bfloat1622float2(*(__nv_bfloat162*)&r0.x);
        float2 a1 = __bfloat1622float2(*(__nv_bfloat162*)&r0.y);
        den += ex;
        acc.x += ex * a0.x; acc.y += ex * a0.y;
        acc.z += ex * a1.x; acc.w += ex * a1.y;
    }
    float inv = 1.f / (den + EPS);
    float4 bias = ((const float4*)b1)[lane];
    float4 r;
    r.x = fmaxf(acc.x * inv + bias.x, 0.f);
    r.y = fmaxf(acc.y * inv + bias.y, 0.f);
    r.z = fmaxf(acc.z * inv + bias.z, 0.f);
    r.w = fmaxf(acc.w * inv + bias.w, 0.f);
    ((float4*)g_agg1)[n * 32 + lane] = r;
}

// ---------------- layer-2 aggregation (fp32) ---------------------------------
__global__ void agg2_kernel(float* __restrict__ out,
                            const float* __restrict__ b2, int N) {
    int n = (blockIdx.x * blockDim.x + threadIdx.x) >> 5;
    int lane = threadIdx.x & 31;
    if (n >= N) return;
    float ad = g_adst2[n];
    int beg = g_rowptr[n];
    int end = g_rowptr[n + 1];

    float acc = 0.f;
    float den = 0.f;
    int i = beg;
    for (; i + 4 <= end; i += 4) {
        int s0 = g_esrc[i], s1 = g_esrc[i + 1], s2 = g_esrc[i + 2], s3 = g_esrc[i + 3];
        float e0 = g_asrc2[s0] + ad, e1 = g_asrc2[s1] + ad;
        float e2 = g_asrc2[s2] + ad, e3 = g_asrc2[s3] + ad;
        float v0 = g_h2[s0 * 32 + lane], v1 = g_h2[s1 * 32 + lane];
        float v2 = g_h2[s2 * 32 + lane], v3 = g_h2[s3 * 32 + lane];
        e0 = (e0 > 0.f) ? e0 : NEG_SLOPE * e0;
        e1 = (e1 > 0.f) ? e1 : NEG_SLOPE * e1;
        e2 = (e2 > 0.f) ? e2 : NEG_SLOPE * e2;
        e3 = (e3 > 0.f) ? e3 : NEG_SLOPE * e3;
        float x0 = __expf(e0), x1 = __expf(e1), x2 = __expf(e2), x3 = __expf(e3);
        den += x0 + x1 + x2 + x3;
        acc += x0 * v0 + x1 * v1 + x2 * v2 + x3 * v3;
    }
    for (; i < end; i++) {
        int s = g_esrc[i];
        float e = g_asrc2[s] + ad;
        e = (e > 0.f) ? e : NEG_SLOPE * e;
        float ex = __expf(e);
        den += ex;
        acc += ex * g_h2[s * 32 + lane];
    }
    out[n * 32 + lane] = acc / (den + EPS) + b2[lane];
}

// ---------------- launch ------------------------------------------------------
extern "C" void kernel_launch(void* const* d_in, const int* in_sizes, int n_in,
                              void* d_out, int out_size) {
    const float* x      = (const float*)d_in[0];
    const int*   ei     = (const int*)  d_in[1];
    const float* W1     = (const float*)d_in[2];
    const float* att_s1 = (const float*)d_in[3];
    const float* att_d1 = (const float*)d_in[4];
    const float* b1     = (const float*)d_in[5];
    const float* W2     = (const float*)d_in[6];
    const float* att_s2 = (const float*)d_in[7];
    const float* att_d2 = (const float*)d_in[8];
    const float* b2     = (const float*)d_in[9];

    int N = in_sizes[0] / IN_DIM;
    int E = in_sizes[1] / 2;
    const int* src = ei;
    const int* dst = ei + E;
    float* out = (float*)d_out;
    int EN = E + N;
    int NB = (N + 1023) / 1024;

    static bool init_done = false;
    static cudaStream_t s2;
    static cudaEvent_t evFork, evJoin;
    if (!init_done) {
        cudaFuncSetAttribute(gemm1_kernel, cudaFuncAttributeMaxDynamicSharedMemorySize, GEMM1_SMEM);
        cudaFuncSetAttribute(gemm2_kernel, cudaFuncAttributeMaxDynamicSharedMemorySize, GEMM2_SMEM);
        cudaStreamCreateWithFlags(&s2, cudaStreamNonBlocking);
        cudaEventCreateWithFlags(&evFork, cudaEventDisableTiming);
        cudaEventCreateWithFlags(&evJoin, cudaEventDisableTiming);
        init_done = true;
    }

    // ---- fork: CSR build on s2, GEMM1+attn1 on main stream ----
    cudaEventRecord(evFork, 0);
    cudaStreamWaitEvent(s2, evFork, 0);

    zero_deg_kernel<<<(N + 255) / 256, 256, 0, s2>>>(N);
    hist_kernel<<<(EN + 255) / 256, 256, 0, s2>>>(dst, E, EN);
    scan1_kernel<<<NB, 1024, 0, s2>>>(N);
    scan2_kernel<<<1, 128, 0, s2>>>(NB);
    scan3_kernel<<<(N + 255) / 256, 256, 0, s2>>>(N, EN);
    scatter_kernel<<<(EN + 255) / 256, 256, 0, s2>>>(src, dst, E, EN);
    cudaEventRecord(evJoin, s2);

    gemm1_kernel<<<(N + 63) / 64, 256, GEMM1_SMEM>>>(x, W1, N);
    attn1_kernel<<<(N * 32 + 255) / 256, 256>>>(att_s1, att_d1, N);

    // ---- join ----
    cudaStreamWaitEvent(0, evJoin, 0);

    agg1_kernel<<<(N * 32 + 255) / 256, 256>>>(b1, N);

    // ---- layer 2 ----
    gemm2_kernel<<<(N + 63) / 64, 256, GEMM2_SMEM>>>(W2, N);
    attn2_kernel<<<(N * 32 + 255) / 256, 256>>>(att_s2, att_d2, N);
    agg2_kernel<<<(N * 32 + 255) / 256, 256>>>(out, b2, N);
}

// round 5
// speedup vs baseline: 2.7888x; 1.0051x over previous
#include <cuda_runtime.h>
#include <cuda_bf16.h>
#include <mma.h>
#include <stdint.h>

using namespace nvcuda;

#define MAXN 100000
#define NPAD (MAXN + 64)
#define MAXE 1600000
#define IN_DIM 128
#define HC 128
#define OUT_DIM 32
#define HEADS 4
#define NEG_SLOPE 0.2f
#define EPS 1e-16f

#define LDA 136
#define LDB1 136
#define LDB2 40
#define GEMM1_SMEM ((64*LDA*2 + 128*LDB1*2) * 2)   // 104448 B (>= 64*128*4 out stage)
#define GEMM2_SMEM ((64*LDA*2 + 128*LDB2*2) * 2)   // 55296 B  (>= 64*32*4 out stage)

// ---------------- scratch (device globals) -----------------------------------
__device__ float g_h1[NPAD * HC];       // x @ W1
__device__ float g_agg1[NPAD * HC];     // layer-1 output h1' (relu'd)
__device__ float g_h2[NPAD * OUT_DIM];  // h1' @ W2
__device__ float g_asrc1[MAXN * HEADS];
__device__ float g_adst1[MAXN * HEADS];
__device__ float g_asrc2[MAXN];
__device__ float g_adst2[MAXN];
// CSR scratch
__device__ int g_deg[MAXN];
__device__ int g_rowptr[MAXN + 1];
__device__ int g_cursor[MAXN];
__device__ int g_esrc[MAXE + MAXN];
__device__ int g_btot[128];
__device__ int g_boff[128];

// ---------------- CSR build ---------------------------------------------------
__global__ void zero_deg_kernel(int N) {
    int t = blockIdx.x * blockDim.x + threadIdx.x;
    if (t < N) g_deg[t] = 0;
}

__global__ void hist_kernel(const int* __restrict__ dst, int E, int EN) {
    int t = blockIdx.x * blockDim.x + threadIdx.x;
    if (t >= EN) return;
    int d = (t < E) ? dst[t] : (t - E);
    atomicAdd(&g_deg[d], 1);
}

__global__ void scan1_kernel(int N) {
    __shared__ int sh[1024];
    int i = blockIdx.x * 1024 + threadIdx.x;
    int v = (i < N) ? g_deg[i] : 0;
    sh[threadIdx.x] = v;
    __syncthreads();
#pragma unroll
    for (int off = 1; off < 1024; off <<= 1) {
        int t = (threadIdx.x >= off) ? sh[threadIdx.x - off] : 0;
        __syncthreads();
        sh[threadIdx.x] += t;
        __syncthreads();
    }
    if (i < N) g_rowptr[i] = sh[threadIdx.x] - v;
    if (threadIdx.x == 1023) g_btot[blockIdx.x] = sh[1023];
}

__global__ void scan2_kernel(int NB) {
    __shared__ int sh[128];
    int t = threadIdx.x;
    int v = (t < NB) ? g_btot[t] : 0;
    sh[t] = v;
    __syncthreads();
#pragma unroll
    for (int off = 1; off < 128; off <<= 1) {
        int u = (t >= off) ? sh[t - off] : 0;
        __syncthreads();
        sh[t] += u;
        __syncthreads();
    }
    if (t < NB) g_boff[t] = sh[t] - v;
}

__global__ void scan3_kernel(int N, int EN) {
    int i = blockIdx.x * blockDim.x + threadIdx.x;
    if (i < N) {
        int r = g_rowptr[i] + g_boff[i >> 10];
        g_rowptr[i] = r;
        g_cursor[i] = r;
    }
    if (i == 0) g_rowptr[N] = EN;
}

__global__ void scatter_kernel(const int* __restrict__ src,
                               const int* __restrict__ dst, int E, int EN) {
    int t = blockIdx.x * blockDim.x + threadIdx.x;
    if (t >= EN) return;
    int s, d;
    if (t < E) { s = src[t]; d = dst[t]; }
    else       { s = t - E;  d = s; }
    int pos = atomicAdd(&g_cursor[d], 1);
    g_esrc[pos] = s;
}

// ---------------- GEMM1 + fused attn1 ----------------------------------------
// h1[N,128] = x @ W1; asrc1/adst1 computed from the out tile in smem.
__global__ void gemm1_kernel(const float* __restrict__ x,
                             const float* __restrict__ W,
                             const float* __restrict__ att_s,
                             const float* __restrict__ att_d, int N) {
    extern __shared__ __nv_bfloat16 sm[];
    __nv_bfloat16* Ahi = sm;
    __nv_bfloat16* Alo = Ahi + 64 * LDA;
    __nv_bfloat16* Bhi = Alo + 64 * LDA;
    __nv_bfloat16* Blo = Bhi + 128 * LDB1;
    float* outs = (float*)sm;   // reused after MMA: 64*128 fp32 = 32KB
    int tid = threadIdx.x;
    int row0 = blockIdx.x * 64;

    for (int i = tid; i < 128 * 128; i += 256) {
        int r = i >> 7, c = i & 127;
        float v = W[i];
        __nv_bfloat16 h = __float2bfloat16(v);
        Bhi[r * LDB1 + c] = h;
        Blo[r * LDB1 + c] = __float2bfloat16(v - __bfloat162float(h));
    }
    for (int i = tid; i < 64 * 128; i += 256) {
        int r = i >> 7, c = i & 127;
        int g = row0 + r;
        float v = (g < N) ? x[(size_t)g * 128 + c] : 0.f;
        __nv_bfloat16 h = __float2bfloat16(v);
        Ahi[r * LDA + c] = h;
        Alo[r * LDA + c] = __float2bfloat16(v - __bfloat162float(h));
    }
    __syncthreads();

    int w = tid >> 5;
    int lane = tid & 31;
    int wr = w >> 1, wc = w & 1;
    wmma::fragment<wmma::accumulator, 16, 16, 16, float> acc[4];
#pragma unroll
    for (int i = 0; i < 4; i++) wmma::fill_fragment(acc[i], 0.f);

#pragma unroll
    for (int k = 0; k < 8; k++) {
        wmma::fragment<wmma::matrix_a, 16, 16, 16, __nv_bfloat16, wmma::row_major> ah, al;
        wmma::load_matrix_sync(ah, Ahi + (wr * 16) * LDA + k * 16, LDA);
        wmma::load_matrix_sync(al, Alo + (wr * 16) * LDA + k * 16, LDA);
#pragma unroll
        for (int ct = 0; ct < 4; ct++) {
            wmma::fragment<wmma::matrix_b, 16, 16, 16, __nv_bfloat16, wmma::row_major> bh, bl;
            wmma::load_matrix_sync(bh, Bhi + (k * 16) * LDB1 + wc * 64 + ct * 16, LDB1);
            wmma::load_matrix_sync(bl, Blo + (k * 16) * LDB1 + wc * 64 + ct * 16, LDB1);
            wmma::mma_sync(acc[ct], ah, bh, acc[ct]);
            wmma::mma_sync(acc[ct], al, bh, acc[ct]);
            wmma::mma_sync(acc[ct], ah, bl, acc[ct]);
        }
    }

    // global store
    float* outp = g_h1 + (size_t)(row0 + wr * 16) * 128 + wc * 64;
#pragma unroll
    for (int ct = 0; ct < 4; ct++)
        wmma::store_matrix_sync(outp + ct * 16, acc[ct], 128, wmma::mem_row_major);

    // stage out tile in smem (reuse A/B area) for attention dots
    __syncthreads();
#pragma unroll
    for (int ct = 0; ct < 4; ct++)
        wmma::store_matrix_sync(outs + (wr * 16) * 128 + wc * 64 + ct * 16,
                                acc[ct], 128, wmma::mem_row_major);
    __syncthreads();

    // fused attn1: warp w handles rows w*8 .. w*8+7
    float4 as = ((const float4*)att_s)[lane];
    float4 ad = ((const float4*)att_d)[lane];
#pragma unroll
    for (int r8 = 0; r8 < 8; r8++) {
        int r = w * 8 + r8;
        int g = row0 + r;
        float4 hv = ((const float4*)outs)[r * 32 + lane];
        float ps = hv.x * as.x + hv.y * as.y + hv.z * as.z + hv.w * as.w;
        float pd = hv.x * ad.x + hv.y * ad.y + hv.z * ad.z + hv.w * ad.w;
        ps += __shfl_xor_sync(0xFFFFFFFFu, ps, 1);
        pd += __shfl_xor_sync(0xFFFFFFFFu, pd, 1);
        ps += __shfl_xor_sync(0xFFFFFFFFu, ps, 2);
        pd += __shfl_xor_sync(0xFFFFFFFFu, pd, 2);
        ps += __shfl_xor_sync(0xFFFFFFFFu, ps, 4);
        pd += __shfl_xor_sync(0xFFFFFFFFu, pd, 4);
        if ((lane & 7) == 0 && g < N) {
            int h = lane >> 3;
            g_asrc1[g * 4 + h] = ps;
            g_adst1[g * 4 + h] = pd;
        }
    }
}

// ---------------- GEMM2 + fused attn2 ----------------------------------------
__global__ void gemm2_kernel(const float* __restrict__ W,
                             const float* __restrict__ att_s,
                             const float* __restrict__ att_d, int N) {
    extern __shared__ __nv_bfloat16 sm[];
    __nv_bfloat16* Ahi = sm;
    __nv_bfloat16* Alo = Ahi + 64 * LDA;
    __nv_bfloat16* Bhi = Alo + 64 * LDA;
    __nv_bfloat16* Blo = Bhi + 128 * LDB2;
    float* outs = (float*)sm;  // reused: 64*32 fp32 = 8KB
    int tid = threadIdx.x;
    int lane = tid & 31;
    int row0 = blockIdx.x * 64;

    for (int i = tid; i < 128 * 32; i += 256) {
        int r = i >> 5, c = i & 31;
        float v = W[i];
        __nv_bfloat16 h = __float2bfloat16(v);
        Bhi[r * LDB2 + c] = h;
        Blo[r * LDB2 + c] = __float2bfloat16(v - __bfloat162float(h));
    }
    for (int i = tid; i < 64 * 128; i += 256) {
        int r = i >> 7, c = i & 127;
        int g = row0 + r;
        float v = (g < N) ? g_agg1[(size_t)g * 128 + c] : 0.f;
        __nv_bfloat16 h = __float2bfloat16(v);
        Ahi[r * LDA + c] = h;
        Alo[r * LDA + c] = __float2bfloat16(v - __bfloat162float(h));
    }
    __syncthreads();

    int w = tid >> 5;
    int wr = w & 3, wc = w >> 2;
    wmma::fragment<wmma::accumulator, 16, 16, 16, float> acc;
    wmma::fill_fragment(acc, 0.f);

#pragma unroll
    for (int k = 0; k < 8; k++) {
        wmma::fragment<wmma::matrix_a, 16, 16, 16, __nv_bfloat16, wmma::row_major> ah, al;
        wmma::fragment<wmma::matrix_b, 16, 16, 16, __nv_bfloat16, wmma::row_major> bh, bl;
        wmma::load_matrix_sync(ah, Ahi + (wr * 16) * LDA + k * 16, LDA);
        wmma::load_matrix_sync(al, Alo + (wr * 16) * LDA + k * 16, LDA);
        wmma::load_matrix_sync(bh, Bhi + (k * 16) * LDB2 + wc * 16, LDB2);
        wmma::load_matrix_sync(bl, Blo + (k * 16) * LDB2 + wc * 16, LDB2);
        wmma::mma_sync(acc, ah, bh, acc);
        wmma::mma_sync(acc, al, bh, acc);
        wmma::mma_sync(acc, ah, bl, acc);
    }
    float* outp = g_h2 + (size_t)(row0 + wr * 16) * 32 + wc * 16;
    wmma::store_matrix_sync(outp, acc, 32, wmma::mem_row_major);

    __syncthreads();
    wmma::store_matrix_sync(outs + (wr * 16) * 32 + wc * 16, acc, 32, wmma::mem_row_major);
    __syncthreads();

    // fused attn2: warp w handles rows w*8 .. w*8+7 (lane = col)
    float asv = att_s[lane];
    float adv = att_d[lane];
#pragma unroll
    for (int r8 = 0; r8 < 8; r8++) {
        int r = w * 8 + r8;
        int g = row0 + r;
        float hv = outs[r * 32 + lane];
        float ps = hv * asv;
        float pd = hv * adv;
#pragma unroll
        for (int o = 16; o > 0; o >>= 1) {
            ps += __shfl_xor_sync(0xFFFFFFFFu, ps, o);
            pd += __shfl_xor_sync(0xFFFFFFFFu, pd, o);
        }
        if (lane == 0 && g < N) {
            g_asrc2[g] = ps;
            g_adst2[g] = pd;
        }
    }
}

// ---------------- layer-1 aggregation (warp-staged edges, fp32 gather) -------
__global__ void agg1_kernel(const float* __restrict__ b1, int N) {
    int n = (blockIdx.x * blockDim.x + threadIdx.x) >> 5;
    int lane = threadIdx.x & 31;
    if (n >= N) return;
    int h = lane >> 3;
    float ad = g_adst1[n * 4 + h];
    int beg = g_rowptr[n];
    int end = g_rowptr[n + 1];
    const float4* h4 = (const float4*)g_h1;

    float4 acc = make_float4(0.f, 0.f, 0.f, 0.f);
    float den = 0.f;

    for (int base = beg; base < end; base += 32) {
        int m = end - base; if (m > 32) m = 32;
        int sv = (base + lane < end) ? g_esrc[base + lane] : 0;
        int j = 0;
        for (; j + 4 <= m; j += 4) {
            int s0 = __shfl_sync(0xFFFFFFFFu, sv, j);
            int s1 = __shfl_sync(0xFFFFFFFFu, sv, j + 1);
            int s2 = __shfl_sync(0xFFFFFFFFu, sv, j + 2);
            int s3 = __shfl_sync(0xFFFFFFFFu, sv, j + 3);
            float e0 = g_asrc1[s0 * 4 + h] + ad;
            float e1 = g_asrc1[s1 * 4 + h] + ad;
            float e2 = g_asrc1[s2 * 4 + h] + ad;
            float e3 = g_asrc1[s3 * 4 + h] + ad;
            float4 v0 = h4[s0 * 32 + lane];
            float4 v1 = h4[s1 * 32 + lane];
            float4 v2 = h4[s2 * 32 + lane];
            float4 v3 = h4[s3 * 32 + lane];
            e0 = (e0 > 0.f) ? e0 : NEG_SLOPE * e0;
            e1 = (e1 > 0.f) ? e1 : NEG_SLOPE * e1;
            e2 = (e2 > 0.f) ? e2 : NEG_SLOPE * e2;
            e3 = (e3 > 0.f) ? e3 : NEG_SLOPE * e3;
            float x0 = __expf(e0), x1 = __expf(e1);
            float x2 = __expf(e2), x3 = __expf(e3);
            den += x0 + x1 + x2 + x3;
            acc.x += x0 * v0.x + x1 * v1.x + x2 * v2.x + x3 * v3.x;
            acc.y += x0 * v0.y + x1 * v1.y + x2 * v2.y + x3 * v3.y;
            acc.z += x0 * v0.z + x1 * v1.z + x2 * v2.z + x3 * v3.z;
            acc.w += x0 * v0.w + x1 * v1.w + x2 * v2.w + x3 * v3.w;
        }
        for (; j < m; j++) {
            int s = __shfl_sync(0xFFFFFFFFu, sv, j);
            float e = g_asrc1[s * 4 + h] + ad;
            e = (e > 0.f) ? e : NEG_SLOPE * e;
            float ex = __expf(e);
            float4 v = h4[s * 32 + lane];
            den += ex;
            acc.x += ex * v.x; acc.y += ex * v.y;
            acc.z += ex * v.z; acc.w += ex * v.w;
        }
    }
    float inv = 1.f / (den + EPS);
    float4 bias = ((const float4*)b1)[lane];
    float4 r;
    r.x = fmaxf(acc.x * inv + bias.x, 0.f);
    r.y = fmaxf(acc.y * inv + bias.y, 0.f);
    r.z = fmaxf(acc.z * inv + bias.z, 0.f);
    r.w = fmaxf(acc.w * inv + bias.w, 0.f);
    ((float4*)g_agg1)[n * 32 + lane] = r;
}

// ---------------- layer-2 aggregation (staged edges + staged asrc) -----------
__global__ void agg2_kernel(float* __restrict__ out,
                            const float* __restrict__ b2, int N) {
    int n = (blockIdx.x * blockDim.x + threadIdx.x) >> 5;
    int lane = threadIdx.x & 31;
    if (n >= N) return;
    float ad = g_adst2[n];
    int beg = g_rowptr[n];
    int end = g_rowptr[n + 1];

    float acc = 0.f;
    float den = 0.f;
    for (int base = beg; base < end; base += 32) {
        int m = end - base; if (m > 32) m = 32;
        int sv = 0; float av = 0.f;
        if (base + lane < end) {
            sv = g_esrc[base + lane];
            av = g_asrc2[sv];
        }
        int j = 0;
        for (; j + 4 <= m; j += 4) {
            int s0 = __shfl_sync(0xFFFFFFFFu, sv, j);
            int s1 = __shfl_sync(0xFFFFFFFFu, sv, j + 1);
            int s2 = __shfl_sync(0xFFFFFFFFu, sv, j + 2);
            int s3 = __shfl_sync(0xFFFFFFFFu, sv, j + 3);
            float e0 = __shfl_sync(0xFFFFFFFFu, av, j) + ad;
            float e1 = __shfl_sync(0xFFFFFFFFu, av, j + 1) + ad;
            float e2 = __shfl_sync(0xFFFFFFFFu, av, j + 2) + ad;
            float e3 = __shfl_sync(0xFFFFFFFFu, av, j + 3) + ad;
            float v0 = g_h2[s0 * 32 + lane];
            float v1 = g_h2[s1 * 32 + lane];
            float v2 = g_h2[s2 * 32 + lane];
            float v3 = g_h2[s3 * 32 + lane];
            e0 = (e0 > 0.f) ? e0 : NEG_SLOPE * e0;
            e1 = (e1 > 0.f) ? e1 : NEG_SLOPE * e1;
            e2 = (e2 > 0.f) ? e2 : NEG_SLOPE * e2;
            e3 = (e3 > 0.f) ? e3 : NEG_SLOPE * e3;
            float x0 = __expf(e0), x1 = __expf(e1);
            float x2 = __expf(e2), x3 = __expf(e3);
            den += x0 + x1 + x2 + x3;
            acc += x0 * v0 + x1 * v1 + x2 * v2 + x3 * v3;
        }
        for (; j < m; j++) {
            int s = __shfl_sync(0xFFFFFFFFu, sv, j);
            float e = __shfl_sync(0xFFFFFFFFu, av, j) + ad;
            e = (e > 0.f) ? e : NEG_SLOPE * e;
            float ex = __expf(e);
            den += ex;
            acc += ex * g_h2[s * 32 + lane];
        }
    }
    out[n * 32 + lane] = acc / (den + EPS) + b2[lane];
}

// ---------------- launch ------------------------------------------------------
extern "C" void kernel_launch(void* const* d_in, const int* in_sizes, int n_in,
                              void* d_out, int out_size) {
    const float* x      = (const float*)d_in[0];
    const int*   ei     = (const int*)  d_in[1];
    const float* W1     = (const float*)d_in[2];
    const float* att_s1 = (const float*)d_in[3];
    const float* att_d1 = (const float*)d_in[4];
    const float* b1     = (const float*)d_in[5];
    const float* W2     = (const float*)d_in[6];
    const float* att_s2 = (const float*)d_in[7];
    const float* att_d2 = (const float*)d_in[8];
    const float* b2     = (const float*)d_in[9];

    int N = in_sizes[0] / IN_DIM;
    int E = in_sizes[1] / 2;
    const int* src = ei;
    const int* dst = ei + E;
    float* out = (float*)d_out;
    int EN = E + N;
    int NB = (N + 1023) / 1024;

    static bool init_done = false;
    static cudaStream_t s2;
    static cudaEvent_t evFork, evJoin;
    if (!init_done) {
        cudaFuncSetAttribute(gemm1_kernel, cudaFuncAttributeMaxDynamicSharedMemorySize, GEMM1_SMEM);
        cudaFuncSetAttribute(gemm2_kernel, cudaFuncAttributeMaxDynamicSharedMemorySize, GEMM2_SMEM);
        cudaStreamCreateWithFlags(&s2, cudaStreamNonBlocking);
        cudaEventCreateWithFlags(&evFork, cudaEventDisableTiming);
        cudaEventCreateWithFlags(&evJoin, cudaEventDisableTiming);
        init_done = true;
    }

    // ---- fork: CSR build on s2, GEMM1(+attn1) on main stream ----
    cudaEventRecord(evFork, 0);
    cudaStreamWaitEvent(s2, evFork, 0);

    zero_deg_kernel<<<(N + 255) / 256, 256, 0, s2>>>(N);
    hist_kernel<<<(EN + 255) / 256, 256, 0, s2>>>(dst, E, EN);
    scan1_kernel<<<NB, 1024, 0, s2>>>(N);
    scan2_kernel<<<1, 128, 0, s2>>>(NB);
    scan3_kernel<<<(N + 255) / 256, 256, 0, s2>>>(N, EN);
    scatter_kernel<<<(EN + 255) / 256, 256, 0, s2>>>(src, dst, E, EN);
    cudaEventRecord(evJoin, s2);

    gemm1_kernel<<<(N + 63) / 64, 256, GEMM1_SMEM>>>(x, W1, att_s1, att_d1, N);

    // ---- join ----
    cudaStreamWaitEvent(0, evJoin, 0);

    agg1_kernel<<<(N * 32 + 255) / 256, 256>>>(b1, N);
    gemm2_kernel<<<(N + 63) / 64, 256, GEMM2_SMEM>>>(W2, att_s2, att_d2, N);
    agg2_kernel<<<(N * 32 + 255) / 256, 256>>>(out, b2, N);
}

// round 6
// speedup vs baseline: 2.7903x; 1.0005x over previous
#include <cuda_runtime.h>
#include <cuda_fp16.h>
#include <cuda_bf16.h>
#include <mma.h>
#include <stdint.h>

using namespace nvcuda;

#define MAXN 100000
#define NPAD (MAXN + 64)
#define MAXE 1600000
#define IN_DIM 128
#define HC 128
#define OUT_DIM 32
#define HEADS 4
#define NEG_SLOPE 0.2f
#define EPS 1e-16f

#define LDA 136
#define LDB1 136
#define LDB2 40
#define GEMM1_SMEM ((64*LDA*2 + 128*LDB1*2) * 2)   // >= 64*128*4 fp32 out stage
#define GEMM2_SMEM ((64*LDA*2 + 128*LDB2*2) * 2)   // >= 64*32*4 fp32 out stage

// ---------------- scratch (device globals) -----------------------------------
__device__ __half g_h1h[NPAD * HC];      // x @ W1, fp16 (gather payload)
__device__ float  g_agg1[NPAD * HC];     // layer-1 output h1' (relu'd, fp32)
__device__ __half g_h2h[NPAD * OUT_DIM]; // h1' @ W2, fp16
__device__ float g_asrc1[MAXN * HEADS];
__device__ float g_adst1[MAXN * HEADS];
__device__ float g_asrc2[MAXN];
__device__ float g_adst2[MAXN];
// CSR scratch
__device__ int g_deg[MAXN];
__device__ int g_rowptr[MAXN + 1];   // raw per-block exclusive scan
__device__ int g_cursor[MAXN];       // zero-initialized via memset node
__device__ int g_esrc[MAXE + MAXN];
__device__ int g_btot[128];
__device__ int g_boff[128];

// ---------------- CSR build ---------------------------------------------------
__global__ void hist_kernel(const int* __restrict__ dst, int E, int EN) {
    int t = blockIdx.x * blockDim.x + threadIdx.x;
    if (t >= EN) return;
    int d = (t < E) ? dst[t] : (t - E);
    atomicAdd(&g_deg[d], 1);
}

__global__ void scan1_kernel(int N) {
    __shared__ int sh[1024];
    int i = blockIdx.x * 1024 + threadIdx.x;
    int v = (i < N) ? g_deg[i] : 0;
    sh[threadIdx.x] = v;
    __syncthreads();
#pragma unroll
    for (int off = 1; off < 1024; off <<= 1) {
        int t = (threadIdx.x >= off) ? sh[threadIdx.x - off] : 0;
        __syncthreads();
        sh[threadIdx.x] += t;
        __syncthreads();
    }
    if (i < N) g_rowptr[i] = sh[threadIdx.x] - v;   // exclusive within block
    if (threadIdx.x == 1023) g_btot[blockIdx.x] = sh[1023];
}

__global__ void scan2_kernel(int NB) {
    __shared__ int sh[128];
    int t = threadIdx.x;
    int v = (t < NB) ? g_btot[t] : 0;
    sh[t] = v;
    __syncthreads();
#pragma unroll
    for (int off = 1; off < 128; off <<= 1) {
        int u = (t >= off) ? sh[t - off] : 0;
        __syncthreads();
        sh[t] += u;
        __syncthreads();
    }
    if (t < NB) g_boff[t] = sh[t] - v;              // exclusive block offset
}

// scatter with inline rowptr finalization (rowptr_raw + boff); cursor pre-zeroed
__global__ void scatter_kernel(const int* __restrict__ src,
                               const int* __restrict__ dst, int E, int EN) {
    int t = blockIdx.x * blockDim.x + threadIdx.x;
    if (t >= EN) return;
    int s, d;
    if (t < E) { s = src[t]; d = dst[t]; }
    else       { s = t - E;  d = s; }
    int base = g_rowptr[d] + g_boff[d >> 10];
    int pos = base + atomicAdd(&g_cursor[d], 1);
    g_esrc[pos] = s;
}

__device__ __forceinline__ int row_beg(int n) {
    return g_rowptr[n] + g_boff[n >> 10];
}

// ---------------- GEMM1 + fused attn1 + fp16 store ---------------------------
__global__ void gemm1_kernel(const float* __restrict__ x,
                             const float* __restrict__ W,
                             const float* __restrict__ att_s,
                             const float* __restrict__ att_d, int N) {
    extern __shared__ __nv_bfloat16 sm[];
    __nv_bfloat16* Ahi = sm;
    __nv_bfloat16* Alo = Ahi + 64 * LDA;
    __nv_bfloat16* Bhi = Alo + 64 * LDA;
    __nv_bfloat16* Blo = Bhi + 128 * LDB1;
    float* outs = (float*)sm;   // reused after MMA: 64*128 fp32 = 32KB
    int tid = threadIdx.x;
    int row0 = blockIdx.x * 64;

    for (int i = tid; i < 128 * 128; i += 256) {
        int r = i >> 7, c = i & 127;
        float v = W[i];
        __nv_bfloat16 h = __float2bfloat16(v);
        Bhi[r * LDB1 + c] = h;
        Blo[r * LDB1 + c] = __float2bfloat16(v - __bfloat162float(h));
    }
    for (int i = tid; i < 64 * 128; i += 256) {
        int r = i >> 7, c = i & 127;
        int g = row0 + r;
        float v = (g < N) ? x[(size_t)g * 128 + c] : 0.f;
        __nv_bfloat16 h = __float2bfloat16(v);
        Ahi[r * LDA + c] = h;
        Alo[r * LDA + c] = __float2bfloat16(v - __bfloat162float(h));
    }
    __syncthreads();

    int w = tid >> 5;
    int lane = tid & 31;
    int wr = w >> 1, wc = w & 1;
    wmma::fragment<wmma::accumulator, 16, 16, 16, float> acc[4];
#pragma unroll
    for (int i = 0; i < 4; i++) wmma::fill_fragment(acc[i], 0.f);

#pragma unroll
    for (int k = 0; k < 8; k++) {
        wmma::fragment<wmma::matrix_a, 16, 16, 16, __nv_bfloat16, wmma::row_major> ah, al;
        wmma::load_matrix_sync(ah, Ahi + (wr * 16) * LDA + k * 16, LDA);
        wmma::load_matrix_sync(al, Alo + (wr * 16) * LDA + k * 16, LDA);
#pragma unroll
        for (int ct = 0; ct < 4; ct++) {
            wmma::fragment<wmma::matrix_b, 16, 16, 16, __nv_bfloat16, wmma::row_major> bh, bl;
            wmma::load_matrix_sync(bh, Bhi + (k * 16) * LDB1 + wc * 64 + ct * 16, LDB1);
            wmma::load_matrix_sync(bl, Blo + (k * 16) * LDB1 + wc * 64 + ct * 16, LDB1);
            wmma::mma_sync(acc[ct], ah, bh, acc[ct]);
            wmma::mma_sync(acc[ct], al, bh, acc[ct]);
            wmma::mma_sync(acc[ct], ah, bl, acc[ct]);
        }
    }

    // stage out tile in smem (fp32), then: fp16 store + attention dots
    __syncthreads();
#pragma unroll
    for (int ct = 0; ct < 4; ct++)
        wmma::store_matrix_sync(outs + (wr * 16) * 128 + wc * 64 + ct * 16,
                                acc[ct], 128, wmma::mem_row_major);
    __syncthreads();

    // fp16 global store (only fp16 copy leaves the kernel)
    for (int i = tid; i < 64 * 64; i += 256) {       // 4096 half2
        int r = i >> 6, c2 = i & 63;
        int g = row0 + r;
        if (g < N) {
            float2 f = ((const float2*)outs)[r * 64 + c2];
            ((half2*)g_h1h)[(size_t)g * 64 + c2] = __floats2half2_rn(f.x, f.y);
        }
    }

    // fused attn1: warp w handles rows w*8 .. w*8+7
    float4 as = ((const float4*)att_s)[lane];
    float4 ad = ((const float4*)att_d)[lane];
#pragma unroll
    for (int r8 = 0; r8 < 8; r8++) {
        int r = w * 8 + r8;
        int g = row0 + r;
        float4 hv = ((const float4*)outs)[r * 32 + lane];
        float ps = hv.x * as.x + hv.y * as.y + hv.z * as.z + hv.w * as.w;
        float pd = hv.x * ad.x + hv.y * ad.y + hv.z * ad.z + hv.w * ad.w;
        ps += __shfl_xor_sync(0xFFFFFFFFu, ps, 1);
        pd += __shfl_xor_sync(0xFFFFFFFFu, pd, 1);
        ps += __shfl_xor_sync(0xFFFFFFFFu, ps, 2);
        pd += __shfl_xor_sync(0xFFFFFFFFu, pd, 2);
        ps += __shfl_xor_sync(0xFFFFFFFFu, ps, 4);
        pd += __shfl_xor_sync(0xFFFFFFFFu, pd, 4);
        if ((lane & 7) == 0 && g < N) {
            int h = lane >> 3;
            g_asrc1[g * 4 + h] = ps;
            g_adst1[g * 4 + h] = pd;
        }
    }
}

// ---------------- GEMM2 + fused attn2 + fp16 store ---------------------------
__global__ void gemm2_kernel(const float* __restrict__ W,
                             const float* __restrict__ att_s,
                             const float* __restrict__ att_d, int N) {
    extern __shared__ __nv_bfloat16 sm[];
    __nv_bfloat16* Ahi = sm;
    __nv_bfloat16* Alo = Ahi + 64 * LDA;
    __nv_bfloat16* Bhi = Alo + 64 * LDA;
    __nv_bfloat16* Blo = Bhi + 128 * LDB2;
    float* outs = (float*)sm;  // reused: 64*32 fp32 = 8KB
    int tid = threadIdx.x;
    int lane = tid & 31;
    int row0 = blockIdx.x * 64;

    for (int i = tid; i < 128 * 32; i += 256) {
        int r = i >> 5, c = i & 31;
        float v = W[i];
        __nv_bfloat16 h = __float2bfloat16(v);
        Bhi[r * LDB2 + c] = h;
        Blo[r * LDB2 + c] = __float2bfloat16(v - __bfloat162float(h));
    }
    for (int i = tid; i < 64 * 128; i += 256) {
        int r = i >> 7, c = i & 127;
        int g = row0 + r;
        float v = (g < N) ? g_agg1[(size_t)g * 128 + c] : 0.f;
        __nv_bfloat16 h = __float2bfloat16(v);
        Ahi[r * LDA + c] = h;
        Alo[r * LDA + c] = __float2bfloat16(v - __bfloat162float(h));
    }
    __syncthreads();

    int w = tid >> 5;
    int wr = w & 3, wc = w >> 2;
    wmma::fragment<wmma::accumulator, 16, 16, 16, float> acc;
    wmma::fill_fragment(acc, 0.f);

#pragma unroll
    for (int k = 0; k < 8; k++) {
        wmma::fragment<wmma::matrix_a, 16, 16, 16, __nv_bfloat16, wmma::row_major> ah, al;
        wmma::fragment<wmma::matrix_b, 16, 16, 16, __nv_bfloat16, wmma::row_major> bh, bl;
        wmma::load_matrix_sync(ah, Ahi + (wr * 16) * LDA + k * 16, LDA);
        wmma::load_matrix_sync(al, Alo + (wr * 16) * LDA + k * 16, LDA);
        wmma::load_matrix_sync(bh, Bhi + (k * 16) * LDB2 + wc * 16, LDB2);
        wmma::load_matrix_sync(bl, Blo + (k * 16) * LDB2 + wc * 16, LDB2);
        wmma::mma_sync(acc, ah, bh, acc);
        wmma::mma_sync(acc, al, bh, acc);
        wmma::mma_sync(acc, ah, bl, acc);
    }

    __syncthreads();
    wmma::store_matrix_sync(outs + (wr * 16) * 32 + wc * 16, acc, 32, wmma::mem_row_major);
    __syncthreads();

    // fp16 global store
    for (int i = tid; i < 64 * 16; i += 256) {       // 1024 half2
        int r = i >> 4, c2 = i & 15;
        int g = row0 + r;
        if (g < N) {
            float2 f = ((const float2*)outs)[r * 16 + c2];
            ((half2*)g_h2h)[(size_t)g * 16 + c2] = __floats2half2_rn(f.x, f.y);
        }
    }

    // fused attn2
    float asv = att_s[lane];
    float adv = att_d[lane];
#pragma unroll
    for (int r8 = 0; r8 < 8; r8++) {
        int r = w * 8 + r8;
        int g = row0 + r;
        float hv = outs[r * 32 + lane];
        float ps = hv * asv;
        float pd = hv * adv;
#pragma unroll
        for (int o = 16; o > 0; o >>= 1) {
            ps += __shfl_xor_sync(0xFFFFFFFFu, ps, o);
            pd += __shfl_xor_sync(0xFFFFFFFFu, pd, o);
        }
        if (lane == 0 && g < N) {
            g_asrc2[g] = ps;
            g_adst2[g] = pd;
        }
    }
}

// ---------------- layer-1 aggregation (fp16 gather, fp32 accum) --------------
__global__ void agg1_kernel(const float* __restrict__ b1, int N, int EN) {
    int n = (blockIdx.x * blockDim.x + threadIdx.x) >> 5;
    int lane = threadIdx.x & 31;
    if (n >= N) return;
    int h = lane >> 3;
    float ad = g_adst1[n * 4 + h];
    int beg = row_beg(n);
    int end = (n + 1 < N) ? row_beg(n + 1) : EN;
    const uint2* hb = (const uint2*)g_h1h;   // 4 halfs per lane

    float4 acc = make_float4(0.f, 0.f, 0.f, 0.f);
    float den = 0.f;

    for (int base = beg; base < end; base += 32) {
        int m = end - base; if (m > 32) m = 32;
        int sv = (base + lane < end) ? g_esrc[base + lane] : 0;
        int j = 0;
        for (; j + 4 <= m; j += 4) {
            int s0 = __shfl_sync(0xFFFFFFFFu, sv, j);
            int s1 = __shfl_sync(0xFFFFFFFFu, sv, j + 1);
            int s2 = __shfl_sync(0xFFFFFFFFu, sv, j + 2);
            int s3 = __shfl_sync(0xFFFFFFFFu, sv, j + 3);
            float e0 = g_asrc1[s0 * 4 + h] + ad;
            float e1 = g_asrc1[s1 * 4 + h] + ad;
            float e2 = g_asrc1[s2 * 4 + h] + ad;
            float e3 = g_asrc1[s3 * 4 + h] + ad;
            uint2 r0 = hb[s0 * 32 + lane];
            uint2 r1 = hb[s1 * 32 + lane];
            uint2 r2 = hb[s2 * 32 + lane];
            uint2 r3 = hb[s3 * 32 + lane];
            e0 = (e0 > 0.f) ? e0 : NEG_SLOPE * e0;
            e1 = (e1 > 0.f) ? e1 : NEG_SLOPE * e1;
            e2 = (e2 > 0.f) ? e2 : NEG_SLOPE * e2;
            e3 = (e3 > 0.f) ? e3 : NEG_SLOPE * e3;
            float x0 = __expf(e0), x1 = __expf(e1);
            float x2 = __expf(e2), x3 = __expf(e3);
            den += x0 + x1 + x2 + x3;
            float2 a0 = __half22float2(*(half2*)&r0.x);
            float2 a1 = __half22float2(*(half2*)&r0.y);
            float2 c0 = __half22float2(*(half2*)&r1.x);
            float2 c1 = __half22float2(*(half2*)&r1.y);
            float2 d0 = __half22float2(*(half2*)&r2.x);
            float2 d1 = __half22float2(*(half2*)&r2.y);
            float2 f0 = __half22float2(*(half2*)&r3.x);
            float2 f1 = __half22float2(*(half2*)&r3.y);
            acc.x += x0 * a0.x + x1 * c0.x + x2 * d0.x + x3 * f0.x;
            acc.y += x0 * a0.y + x1 * c0.y + x2 * d0.y + x3 * f0.y;
            acc.z += x0 * a1.x + x1 * c1.x + x2 * d1.x + x3 * f1.x;
            acc.w += x0 * a1.y + x1 * c1.y + x2 * d1.y + x3 * f1.y;
        }
        for (; j < m; j++) {
            int s = __shfl_sync(0xFFFFFFFFu, sv, j);
            float e = g_asrc1[s * 4 + h] + ad;
            e = (e > 0.f) ? e : NEG_SLOPE * e;
            float ex = __expf(e);
            uint2 r0 = hb[s * 32 + lane];
            float2 a0 = __half22float2(*(half2*)&r0.x);
            float2 a1 = __half22float2(*(half2*)&r0.y);
            den += ex;
            acc.x += ex * a0.x; acc.y += ex * a0.y;
            acc.z += ex * a1.x; acc.w += ex * a1.y;
        }
    }
    float inv = 1.f / (den + EPS);
    float4 bias = ((const float4*)b1)[lane];
    float4 r;
    r.x = fmaxf(acc.x * inv + bias.x, 0.f);
    r.y = fmaxf(acc.y * inv + bias.y, 0.f);
    r.z = fmaxf(acc.z * inv + bias.z, 0.f);
    r.w = fmaxf(acc.w * inv + bias.w, 0.f);
    ((float4*)g_agg1)[n * 32 + lane] = r;
}

// ---------------- layer-2 aggregation (fp16 gather) --------------------------
__global__ void agg2_kernel(float* __restrict__ out,
                            const float* __restrict__ b2, int N, int EN) {
    int n = (blockIdx.x * blockDim.x + threadIdx.x) >> 5;
    int lane = threadIdx.x & 31;
    if (n >= N) return;
    float ad = g_adst2[n];
    int beg = row_beg(n);
    int end = (n + 1 < N) ? row_beg(n + 1) : EN;

    float acc = 0.f;
    float den = 0.f;
    for (int base = beg; base < end; base += 32) {
        int m = end - base; if (m > 32) m = 32;
        int sv = 0; float av = 0.f;
        if (base + lane < end) {
            sv = g_esrc[base + lane];
            av = g_asrc2[sv];
        }
        int j = 0;
        for (; j + 4 <= m; j += 4) {
            int s0 = __shfl_sync(0xFFFFFFFFu, sv, j);
            int s1 = __shfl_sync(0xFFFFFFFFu, sv, j + 1);
            int s2 = __shfl_sync(0xFFFFFFFFu, sv, j + 2);
            int s3 = __shfl_sync(0xFFFFFFFFu, sv, j + 3);
            float e0 = __shfl_sync(0xFFFFFFFFu, av, j) + ad;
            float e1 = __shfl_sync(0xFFFFFFFFu, av, j + 1) + ad;
            float e2 = __shfl_sync(0xFFFFFFFFu, av, j + 2) + ad;
            float e3 = __shfl_sync(0xFFFFFFFFu, av, j + 3) + ad;
            float v0 = __half2float(g_h2h[s0 * 32 + lane]);
            float v1 = __half2float(g_h2h[s1 * 32 + lane]);
            float v2 = __half2float(g_h2h[s2 * 32 + lane]);
            float v3 = __half2float(g_h2h[s3 * 32 + lane]);
            e0 = (e0 > 0.f) ? e0 : NEG_SLOPE * e0;
            e1 = (e1 > 0.f) ? e1 : NEG_SLOPE * e1;
            e2 = (e2 > 0.f) ? e2 : NEG_SLOPE * e2;
            e3 = (e3 > 0.f) ? e3 : NEG_SLOPE * e3;
            float x0 = __expf(e0), x1 = __expf(e1);
            float x2 = __expf(e2), x3 = __expf(e3);
            den += x0 + x1 + x2 + x3;
            acc += x0 * v0 + x1 * v1 + x2 * v2 + x3 * v3;
        }
        for (; j < m; j++) {
            int s = __shfl_sync(0xFFFFFFFFu, sv, j);
            float e = __shfl_sync(0xFFFFFFFFu, av, j) + ad;
            e = (e > 0.f) ? e : NEG_SLOPE * e;
            float ex = __expf(e);
            den += ex;
            acc += ex * __half2float(g_h2h[s * 32 + lane]);
        }
    }
    out[n * 32 + lane] = acc / (den + EPS) + b2[lane];
}

// ---------------- launch ------------------------------------------------------
extern "C" void kernel_launch(void* const* d_in, const int* in_sizes, int n_in,
                              void* d_out, int out_size) {
    const float* x      = (const float*)d_in[0];
    const int*   ei     = (const int*)  d_in[1];
    const float* W1     = (const float*)d_in[2];
    const float* att_s1 = (const float*)d_in[3];
    const float* att_d1 = (const float*)d_in[4];
    const float* b1     = (const float*)d_in[5];
    const float* W2     = (const float*)d_in[6];
    const float* att_s2 = (const float*)d_in[7];
    const float* att_d2 = (const float*)d_in[8];
    const float* b2     = (const float*)d_in[9];

    int N = in_sizes[0] / IN_DIM;
    int E = in_sizes[1] / 2;
    const int* src = ei;
    const int* dst = ei + E;
    float* out = (float*)d_out;
    int EN = E + N;
    int NB = (N + 1023) / 1024;

    static bool init_done = false;
    static void *deg_ptr = nullptr, *cur_ptr = nullptr;
    if (!init_done) {
        cudaFuncSetAttribute(gemm1_kernel, cudaFuncAttributeMaxDynamicSharedMemorySize, GEMM1_SMEM);
        cudaFuncSetAttribute(gemm2_kernel, cudaFuncAttributeMaxDynamicSharedMemorySize, GEMM2_SMEM);
        cudaGetSymbolAddress(&deg_ptr, g_deg);
        cudaGetSymbolAddress(&cur_ptr, g_cursor);
        init_done = true;
    }

    // memset nodes (not kernel launches — keeps agg1 as the 6th kernel for ncu)
    cudaMemsetAsync(deg_ptr, 0, (size_t)N * 4, 0);
    cudaMemsetAsync(cur_ptr, 0, (size_t)N * 4, 0);

    // CSR build:     kernels #1..#4
    hist_kernel<<<(EN + 255) / 256, 256>>>(dst, E, EN);
    scan1_kernel<<<NB, 1024>>>(N);
    scan2_kernel<<<1, 128>>>(NB);
    scatter_kernel<<<(EN + 255) / 256, 256>>>(src, dst, E, EN);

    // layer 1:       kernels #5, #6 (ncu -s 5 -c 1 captures agg1)
    gemm1_kernel<<<(N + 63) / 64, 256, GEMM1_SMEM>>>(x, W1, att_s1, att_d1, N);
    agg1_kernel<<<(N * 32 + 255) / 256, 256>>>(b1, N, EN);

    // layer 2
    gemm2_kernel<<<(N + 63) / 64, 256, GEMM2_SMEM>>>(W2, att_s2, att_d2, N);
    agg2_kernel<<<(N * 32 + 255) / 256, 256>>>(out, b2, N, EN);
}